// round 1
// baseline (speedup 1.0000x reference)
#include <cuda_runtime.h>
#include <math.h>

// Problem constants
#define B_   2
#define N_   1024
#define D_   2048
#define H_   8
#define I_   4
#define KD_  128
#define VD_  128
#define HI_  32    // H_*I_

// ---------------------------------------------------------------------------
// Device scratch (allocation-free rule: __device__ globals)
// ---------------------------------------------------------------------------
__device__ float g_q[(size_t)B_ * N_ * HI_ * KD_];   // 8,388,608 floats
__device__ float g_k[(size_t)B_ * N_ * H_  * KD_];   // 2,097,152
__device__ float g_v[(size_t)B_ * N_ * H_  * VD_];   // 2,097,152
__device__ float g_attn[(size_t)B_ * N_ * HI_ * VD_]; // 8,388,608

// ---------------------------------------------------------------------------
// SGEMM: C[M,Nc] = A[M,Kd] * B[Kd,Nc], all row-major fp32.
// BM=BN=128, BK=8, 256 threads, 8x8 register tile per thread.
// ---------------------------------------------------------------------------
__global__ __launch_bounds__(256) void sgemm_kernel(
    const float* __restrict__ A, const float* __restrict__ Bm,
    float* __restrict__ C, int M, int Nc, int Kd)
{
    __shared__ float As[8][128];
    __shared__ float Bs[8][128];

    const int tid  = threadIdx.x;
    const int brow = blockIdx.y * 128;
    const int bcol = blockIdx.x * 128;

    // A tile loads: 128 rows x 8 cols = 1024 floats; float4 along Kd
    const int a_r = tid >> 1;           // 0..127
    const int a_c = (tid & 1) << 2;     // 0 or 4
    // B tile loads: 8 rows x 128 cols; float4 along Nc
    const int b_r = tid >> 5;           // 0..7
    const int b_c = (tid & 31) << 2;    // 0..124

    const int ty = tid >> 4;            // 0..15
    const int tx = tid & 15;            // 0..15

    float acc[8][8];
    #pragma unroll
    for (int i = 0; i < 8; i++)
        #pragma unroll
        for (int j = 0; j < 8; j++) acc[i][j] = 0.f;

    for (int k0 = 0; k0 < Kd; k0 += 8) {
        float4 av = *(const float4*)(A + (size_t)(brow + a_r) * Kd + k0 + a_c);
        As[a_c + 0][a_r] = av.x;
        As[a_c + 1][a_r] = av.y;
        As[a_c + 2][a_r] = av.z;
        As[a_c + 3][a_r] = av.w;
        float4 bv = *(const float4*)(Bm + (size_t)(k0 + b_r) * Nc + bcol + b_c);
        *(float4*)&Bs[b_r][b_c] = bv;
        __syncthreads();

        #pragma unroll
        for (int k = 0; k < 8; k++) {
            float4 a0 = *(const float4*)&As[k][ty * 8];
            float4 a1 = *(const float4*)&As[k][ty * 8 + 4];
            float4 b0 = *(const float4*)&Bs[k][tx * 8];
            float4 b1 = *(const float4*)&Bs[k][tx * 8 + 4];
            float ar[8] = {a0.x, a0.y, a0.z, a0.w, a1.x, a1.y, a1.z, a1.w};
            float br[8] = {b0.x, b0.y, b0.z, b0.w, b1.x, b1.y, b1.z, b1.w};
            #pragma unroll
            for (int i = 0; i < 8; i++)
                #pragma unroll
                for (int j = 0; j < 8; j++)
                    acc[i][j] = fmaf(ar[i], br[j], acc[i][j]);
        }
        __syncthreads();
    }

    #pragma unroll
    for (int i = 0; i < 8; i++) {
        float* crow = C + (size_t)(brow + ty * 8 + i) * Nc + bcol + tx * 8;
        *(float4*)(crow)     = make_float4(acc[i][0], acc[i][1], acc[i][2], acc[i][3]);
        *(float4*)(crow + 4) = make_float4(acc[i][4], acc[i][5], acc[i][6], acc[i][7]);
    }
}

// ---------------------------------------------------------------------------
// RoPE (half-split convention, matching jnp.split into two halves)
// data layout: [B*N][nheads*128]; one thread per (row, head, j<64) pair
// ---------------------------------------------------------------------------
__global__ void rope_kernel(float* __restrict__ data, int nheads, int total)
{
    int idx = blockIdx.x * blockDim.x + threadIdx.x;
    if (idx >= total) return;
    int j    = idx & 63;
    int t    = idx >> 6;
    int head = t % nheads;
    int row  = t / nheads;
    int n    = row % N_;

    float inv = powf(10000.f, -(float)j * (1.f / 64.f));
    float ang = (float)n * inv;
    float s, c;
    sincosf(ang, &s, &c);

    float* p = data + ((size_t)row * nheads + head) * 128;
    float x1 = p[j];
    float x2 = p[j + 64];
    p[j]      = x1 * c - x2 * s;
    p[j + 64] = x1 * s + x2 * c;
}

// ---------------------------------------------------------------------------
// Flash attention, fp32, causal. BM=BN=64, head dim 128.
// Grid: (16 q-tiles, 64 bhi). 256 threads.
// Dynamic smem: Qt[128][64] + Kt[128][64] + Vs[64][128] + S[64][65] + 3*64
// ---------------------------------------------------------------------------
#define FLASH_SMEM_FLOATS (128*64 + 128*64 + 64*128 + 64*65 + 3*64)
#define FLASH_SMEM_BYTES  (FLASH_SMEM_FLOATS * 4)

__global__ __launch_bounds__(256) void flash_attn_kernel(
    const float* __restrict__ q, const float* __restrict__ k,
    const float* __restrict__ v, float* __restrict__ o)
{
    extern __shared__ float sm[];
    float* Qt   = sm;                  // [128][64] transposed
    float* Kt   = Qt + 128 * 64;       // [128][64] transposed
    float* Vs   = Kt + 128 * 64;       // [64][128]
    float* S    = Vs + 64 * 128;       // [64][65] padded
    float* mrow = S + 64 * 65;
    float* lrow = mrow + 64;
    float* arow = lrow + 64;

    const int tid = threadIdx.x;
    const int qt  = blockIdx.x;        // q tile 0..15
    const int bhi = blockIdx.y;        // 0..63
    const int b   = bhi / HI_;
    const int hi  = bhi % HI_;
    const int h   = hi / I_;

    // Load Q tile transposed: Qt[kk][r]
    const float* qbase = q + ((size_t)(b * N_ + qt * 64) * HI_ + hi) * KD_;
    for (int idx = tid; idx < 64 * KD_ / 4; idx += 256) {
        int r = idx >> 5;
        int c = (idx & 31) << 2;
        float4 vv = *(const float4*)(qbase + (size_t)r * HI_ * KD_ + c);
        Qt[(c + 0) * 64 + r] = vv.x;
        Qt[(c + 1) * 64 + r] = vv.y;
        Qt[(c + 2) * 64 + r] = vv.z;
        Qt[(c + 3) * 64 + r] = vv.w;
    }
    if (tid < 64) { mrow[tid] = -1e30f; lrow[tid] = 0.f; }

    float oacc[4][8];
    #pragma unroll
    for (int a = 0; a < 4; a++)
        #pragma unroll
        for (int c = 0; c < 8; c++) oacc[a][c] = 0.f;

    const int sy = tid >> 4;   // 0..15
    const int sx = tid & 15;   // 0..15
    const float scale = 0.088388347648318447f;  // 1/sqrt(128)
    __syncthreads();

    for (int kt = 0; kt <= qt; kt++) {
        // Load K (transposed) and V (natural) tiles
        const float* kbase = k + ((size_t)(b * N_ + kt * 64) * H_ + h) * KD_;
        const float* vbase = v + ((size_t)(b * N_ + kt * 64) * H_ + h) * VD_;
        for (int idx = tid; idx < 64 * KD_ / 4; idx += 256) {
            int r = idx >> 5;
            int c = (idx & 31) << 2;
            float4 kv4 = *(const float4*)(kbase + (size_t)r * H_ * KD_ + c);
            Kt[(c + 0) * 64 + r] = kv4.x;
            Kt[(c + 1) * 64 + r] = kv4.y;
            Kt[(c + 2) * 64 + r] = kv4.z;
            Kt[(c + 3) * 64 + r] = kv4.w;
            float4 vv4 = *(const float4*)(vbase + (size_t)r * H_ * VD_ + c);
            *(float4*)(Vs + r * VD_ + c) = vv4;
        }
        __syncthreads();

        // S = Q K^T, thread computes 4x4 tile at rows sy*4.., cols sx*4..
        float sval[4][4];
        #pragma unroll
        for (int a = 0; a < 4; a++)
            #pragma unroll
            for (int bb = 0; bb < 4; bb++) sval[a][bb] = 0.f;

        #pragma unroll 4
        for (int kk = 0; kk < KD_; kk++) {
            float4 qa = *(const float4*)(Qt + kk * 64 + sy * 4);
            float4 kb = *(const float4*)(Kt + kk * 64 + sx * 4);
            float qr[4] = {qa.x, qa.y, qa.z, qa.w};
            float kr[4] = {kb.x, kb.y, kb.z, kb.w};
            #pragma unroll
            for (int a = 0; a < 4; a++)
                #pragma unroll
                for (int bb = 0; bb < 4; bb++)
                    sval[a][bb] = fmaf(qr[a], kr[bb], sval[a][bb]);
        }

        // Scale + causal mask (only needed on diagonal tile), write to smem
        const bool diag = (kt == qt);
        #pragma unroll
        for (int a = 0; a < 4; a++) {
            #pragma unroll
            for (int bb = 0; bb < 4; bb++) {
                float s = sval[a][bb] * scale;
                if (diag && (sx * 4 + bb) > (sy * 4 + a)) s = -1e30f;
                sval[a][bb] = s;
                S[(sy * 4 + a) * 65 + sx * 4 + bb] = s;
            }
        }
        __syncthreads();

        // Row max + correction factor
        if (tid < 64) {
            float m  = mrow[tid];
            float mx = m;
            #pragma unroll 8
            for (int c = 0; c < 64; c++) mx = fmaxf(mx, S[tid * 65 + c]);
            arow[tid] = __expf(m - mx);
            mrow[tid] = mx;
        }
        __syncthreads();

        // exp in place (from registers)
        #pragma unroll
        for (int a = 0; a < 4; a++) {
            float mx = mrow[sy * 4 + a];
            #pragma unroll
            for (int bb = 0; bb < 4; bb++)
                S[(sy * 4 + a) * 65 + sx * 4 + bb] = __expf(sval[a][bb] - mx);
        }
        __syncthreads();

        // Row sum (l update) concurrent with O rescale + PV
        if (tid < 64) {
            float sum = 0.f;
            #pragma unroll 8
            for (int c = 0; c < 64; c++) sum += S[tid * 65 + c];
            lrow[tid] = arow[tid] * lrow[tid] + sum;
        }

        // Rescale O accumulators
        #pragma unroll
        for (int a = 0; a < 4; a++) {
            float al = arow[sy * 4 + a];
            #pragma unroll
            for (int c = 0; c < 8; c++) oacc[a][c] *= al;
        }

        // O += P * V : rows sy*4.., cols sx*8..
        #pragma unroll 2
        for (int kk = 0; kk < 64; kk++) {
            float4 v0 = *(const float4*)(Vs + kk * VD_ + sx * 8);
            float4 v1 = *(const float4*)(Vs + kk * VD_ + sx * 8 + 4);
            float vr[8] = {v0.x, v0.y, v0.z, v0.w, v1.x, v1.y, v1.z, v1.w};
            float p[4];
            #pragma unroll
            for (int a = 0; a < 4; a++) p[a] = S[(sy * 4 + a) * 65 + kk];
            #pragma unroll
            for (int a = 0; a < 4; a++)
                #pragma unroll
                for (int c = 0; c < 8; c++)
                    oacc[a][c] = fmaf(p[a], vr[c], oacc[a][c]);
        }
        __syncthreads();
    }

    // Final normalize + write
    float* obase = o + ((size_t)(b * N_ + qt * 64) * HI_ + hi) * VD_;
    #pragma unroll
    for (int a = 0; a < 4; a++) {
        float inv = 1.f / lrow[sy * 4 + a];
        float* orow = obase + (size_t)(sy * 4 + a) * HI_ * VD_ + sx * 8;
        *(float4*)(orow)     = make_float4(oacc[a][0] * inv, oacc[a][1] * inv,
                                           oacc[a][2] * inv, oacc[a][3] * inv);
        *(float4*)(orow + 4) = make_float4(oacc[a][4] * inv, oacc[a][5] * inv,
                                           oacc[a][6] * inv, oacc[a][7] * inv);
    }
}

// ---------------------------------------------------------------------------
// Launch
// ---------------------------------------------------------------------------
extern "C" void kernel_launch(void* const* d_in, const int* in_sizes, int n_in,
                              void* d_out, int out_size)
{
    const float* x  = (const float*)d_in[0];   // [B,N,D]
    const float* Wq = (const float*)d_in[1];   // [D,H,I,K]  -> [2048,4096]
    const float* Wk = (const float*)d_in[2];   // [D,H,K]    -> [2048,1024]
    const float* Wv = (const float*)d_in[3];   // [D,H,V]    -> [2048,1024]
    const float* Wo = (const float*)d_in[4];   // [H,I,V,D]  -> [4096,2048]
    float* out = (float*)d_out;                // [B,N,D]    -> [2048,2048]

    float *q, *k, *v, *attn;
    cudaGetSymbolAddress((void**)&q, g_q);
    cudaGetSymbolAddress((void**)&k, g_k);
    cudaGetSymbolAddress((void**)&v, g_v);
    cudaGetSymbolAddress((void**)&attn, g_attn);

    const int M = B_ * N_;   // 2048

    // Projections
    sgemm_kernel<<<dim3(4096 / 128, M / 128), 256>>>(x, Wq, q, M, 4096, D_);
    sgemm_kernel<<<dim3(1024 / 128, M / 128), 256>>>(x, Wk, k, M, 1024, D_);
    sgemm_kernel<<<dim3(1024 / 128, M / 128), 256>>>(x, Wv, v, M, 1024, D_);

    // RoPE on q and k
    {
        int total_q = B_ * N_ * HI_ * 64;
        rope_kernel<<<(total_q + 255) / 256, 256>>>(q, HI_, total_q);
        int total_k = B_ * N_ * H_ * 64;
        rope_kernel<<<(total_k + 255) / 256, 256>>>(k, H_, total_k);
    }

    // Flash attention
    cudaFuncSetAttribute(flash_attn_kernel,
                         cudaFuncAttributeMaxDynamicSharedMemorySize,
                         FLASH_SMEM_BYTES);
    flash_attn_kernel<<<dim3(16, 64), 256, FLASH_SMEM_BYTES>>>(q, k, v, attn);

    // Output projection
    sgemm_kernel<<<dim3(2048 / 128, M / 128), 256>>>(attn, Wo, out, M, 2048, 4096);
}

// round 2
// speedup vs baseline: 1.5718x; 1.5718x over previous
#include <cuda_runtime.h>
#include <cuda_bf16.h>
#include <math.h>
#include <stdint.h>

// Problem constants
#define B_   2
#define N_   1024
#define D_   2048
#define H_   8
#define I_   4
#define KD_  128
#define VD_  128
#define HI_  32    // H_*I_

// ---------------------------------------------------------------------------
// Device scratch
// ---------------------------------------------------------------------------
__device__ float g_q[(size_t)B_ * N_ * HI_ * KD_];
__device__ float g_k[(size_t)B_ * N_ * H_  * KD_];
__device__ float g_v[(size_t)B_ * N_ * H_  * VD_];
__device__ float g_attn[(size_t)B_ * N_ * HI_ * VD_];

// ---------------------------------------------------------------------------
// Tensor-core helpers (HMMA mma.sync, bf16 in / fp32 accum)
// ---------------------------------------------------------------------------
__device__ __forceinline__ void ldsm4(uint32_t* r, const __nv_bfloat16* p) {
    uint32_t a = (uint32_t)__cvta_generic_to_shared(p);
    asm volatile("ldmatrix.sync.aligned.m8n8.x4.shared.b16 {%0,%1,%2,%3}, [%4];"
                 : "=r"(r[0]), "=r"(r[1]), "=r"(r[2]), "=r"(r[3]) : "r"(a));
}
__device__ __forceinline__ void ldsm4t(uint32_t* r, const __nv_bfloat16* p) {
    uint32_t a = (uint32_t)__cvta_generic_to_shared(p);
    asm volatile("ldmatrix.sync.aligned.m8n8.x4.trans.shared.b16 {%0,%1,%2,%3}, [%4];"
                 : "=r"(r[0]), "=r"(r[1]), "=r"(r[2]), "=r"(r[3]) : "r"(a));
}
__device__ __forceinline__ void mma16816(float* c, const uint32_t* a, const uint32_t* b) {
    asm volatile("mma.sync.aligned.m16n8k16.row.col.f32.bf16.bf16.f32 "
                 "{%0,%1,%2,%3}, {%4,%5,%6,%7}, {%8,%9}, {%0,%1,%2,%3};"
                 : "+f"(c[0]), "+f"(c[1]), "+f"(c[2]), "+f"(c[3])
                 : "r"(a[0]), "r"(a[1]), "r"(a[2]), "r"(a[3]),
                   "r"(b[0]), "r"(b[1]));
}

// ---------------------------------------------------------------------------
// Split-bf16 GEMM: C[M,Nc] = A[M,Kd] * B[Kd,Nc], fp32 in/out.
// A = Ah + Al, B = Bh + Bl (bf16); C = Ah*Bh + Ah*Bl + Al*Bh (fp32 accum).
// BM=BN=128, BK=32, 256 threads. 8 warps in 4x2 (m x n), warp tile 32x64.
// ---------------------------------------------------------------------------
#define ASTR 40    // bf16 elems per A smem row (80B, odd multiple of 16B)
#define BSTR 136   // bf16 elems per B smem row (272B, odd multiple of 16B)

__global__ __launch_bounds__(256) void bgemm_kernel(
    const float* __restrict__ A, const float* __restrict__ Bm,
    float* __restrict__ C, int M, int Nc, int Kd)
{
    __shared__ __nv_bfloat16 Ah[128 * ASTR];
    __shared__ __nv_bfloat16 Al[128 * ASTR];
    __shared__ __nv_bfloat16 Bh[32 * BSTR];
    __shared__ __nv_bfloat16 Bl[32 * BSTR];

    const int tid    = threadIdx.x;
    const int lane   = tid & 31;
    const int wid    = tid >> 5;
    const int warp_m = wid & 3;     // 0..3 -> rows warp_m*32
    const int warp_n = wid >> 2;    // 0..1 -> cols warp_n*64
    const int brow   = blockIdx.y * 128;
    const int bcol   = blockIdx.x * 128;

    // ldmatrix per-lane addressing: row add = lane&15, col add = (lane>=16)*8
    const int lr = lane & 15;
    const int lc = (lane >> 4) << 3;

    float acc[2][8][4];
    #pragma unroll
    for (int im = 0; im < 2; im++)
        #pragma unroll
        for (int jn = 0; jn < 8; jn++)
            #pragma unroll
            for (int t = 0; t < 4; t++) acc[im][jn][t] = 0.f;

    for (int k0 = 0; k0 < Kd; k0 += 32) {
        // --- A tile: 128 rows x 32 cols fp32 -> hi/lo bf16
        #pragma unroll
        for (int p = 0; p < 4; p++) {
            int r = p * 32 + (tid >> 3);
            int c = (tid & 7) << 2;
            float4 v = *(const float4*)(A + (size_t)(brow + r) * Kd + k0 + c);
            __nv_bfloat16 h0 = __float2bfloat16(v.x);
            __nv_bfloat16 h1 = __float2bfloat16(v.y);
            __nv_bfloat16 h2 = __float2bfloat16(v.z);
            __nv_bfloat16 h3 = __float2bfloat16(v.w);
            Ah[r * ASTR + c + 0] = h0;
            Ah[r * ASTR + c + 1] = h1;
            Ah[r * ASTR + c + 2] = h2;
            Ah[r * ASTR + c + 3] = h3;
            Al[r * ASTR + c + 0] = __float2bfloat16(v.x - __bfloat162float(h0));
            Al[r * ASTR + c + 1] = __float2bfloat16(v.y - __bfloat162float(h1));
            Al[r * ASTR + c + 2] = __float2bfloat16(v.z - __bfloat162float(h2));
            Al[r * ASTR + c + 3] = __float2bfloat16(v.w - __bfloat162float(h3));
        }
        // --- B tile: 32 rows x 128 cols
        #pragma unroll
        for (int p = 0; p < 4; p++) {
            int r = p * 8 + (tid >> 5);
            int c = (tid & 31) << 2;
            float4 v = *(const float4*)(Bm + (size_t)(k0 + r) * Nc + bcol + c);
            __nv_bfloat16 h0 = __float2bfloat16(v.x);
            __nv_bfloat16 h1 = __float2bfloat16(v.y);
            __nv_bfloat16 h2 = __float2bfloat16(v.z);
            __nv_bfloat16 h3 = __float2bfloat16(v.w);
            Bh[r * BSTR + c + 0] = h0;
            Bh[r * BSTR + c + 1] = h1;
            Bh[r * BSTR + c + 2] = h2;
            Bh[r * BSTR + c + 3] = h3;
            Bl[r * BSTR + c + 0] = __float2bfloat16(v.x - __bfloat162float(h0));
            Bl[r * BSTR + c + 1] = __float2bfloat16(v.y - __bfloat162float(h1));
            Bl[r * BSTR + c + 2] = __float2bfloat16(v.z - __bfloat162float(h2));
            Bl[r * BSTR + c + 3] = __float2bfloat16(v.w - __bfloat162float(h3));
        }
        __syncthreads();

        #pragma unroll
        for (int ks = 0; ks < 2; ks++) {
            uint32_t ah[2][4], al[2][4];
            #pragma unroll
            for (int im = 0; im < 2; im++) {
                const int ar = (warp_m * 32 + im * 16 + lr) * ASTR + ks * 16 + lc;
                ldsm4(ah[im], &Ah[ar]);
                ldsm4(al[im], &Al[ar]);
            }
            #pragma unroll
            for (int jp = 0; jp < 4; jp++) {
                uint32_t bh[4], bl[4];
                const int boff = (ks * 16 + lr) * BSTR + warp_n * 64 + jp * 16 + lc;
                ldsm4t(bh, &Bh[boff]);
                ldsm4t(bl, &Bl[boff]);
                #pragma unroll
                for (int im = 0; im < 2; im++) {
                    mma16816(acc[im][jp * 2 + 0], ah[im], bh + 0);
                    mma16816(acc[im][jp * 2 + 1], ah[im], bh + 2);
                    mma16816(acc[im][jp * 2 + 0], ah[im], bl + 0);
                    mma16816(acc[im][jp * 2 + 1], ah[im], bl + 2);
                    mma16816(acc[im][jp * 2 + 0], al[im], bh + 0);
                    mma16816(acc[im][jp * 2 + 1], al[im], bh + 2);
                }
            }
        }
        __syncthreads();
    }

    // Epilogue: fragment (r = lane/4, c = (lane%4)*2)
    const int r0 = lane >> 2;
    const int c0 = (lane & 3) << 1;
    #pragma unroll
    for (int im = 0; im < 2; im++) {
        #pragma unroll
        for (int jn = 0; jn < 8; jn++) {
            float* cp = C + (size_t)(brow + warp_m * 32 + im * 16 + r0) * Nc
                          + bcol + warp_n * 64 + jn * 8 + c0;
            *(float2*)cp              = make_float2(acc[im][jn][0], acc[im][jn][1]);
            *(float2*)(cp + 8 * (size_t)Nc) = make_float2(acc[im][jn][2], acc[im][jn][3]);
        }
    }
}

// ---------------------------------------------------------------------------
// RoPE (half-split convention)
// ---------------------------------------------------------------------------
__global__ void rope_kernel(float* __restrict__ data, int nheads, int total)
{
    int idx = blockIdx.x * blockDim.x + threadIdx.x;
    if (idx >= total) return;
    int j    = idx & 63;
    int t    = idx >> 6;
    int head = t % nheads;
    int row  = t / nheads;
    int n    = row % N_;

    float inv = powf(10000.f, -(float)j * (1.f / 64.f));
    float ang = (float)n * inv;
    float s, c;
    sincosf(ang, &s, &c);

    float* p = data + ((size_t)row * nheads + head) * 128;
    float x1 = p[j];
    float x2 = p[j + 64];
    p[j]      = x1 * c - x2 * s;
    p[j + 64] = x1 * s + x2 * c;
}

// ---------------------------------------------------------------------------
// Flash attention, fp32, causal. BM=BN=64, head dim 128. (unchanged)
// ---------------------------------------------------------------------------
#define FLASH_SMEM_FLOATS (128*64 + 128*64 + 64*128 + 64*65 + 3*64)
#define FLASH_SMEM_BYTES  (FLASH_SMEM_FLOATS * 4)

__global__ __launch_bounds__(256) void flash_attn_kernel(
    const float* __restrict__ q, const float* __restrict__ k,
    const float* __restrict__ v, float* __restrict__ o)
{
    extern __shared__ float sm[];
    float* Qt   = sm;
    float* Kt   = Qt + 128 * 64;
    float* Vs   = Kt + 128 * 64;
    float* S    = Vs + 64 * 128;
    float* mrow = S + 64 * 65;
    float* lrow = mrow + 64;
    float* arow = lrow + 64;

    const int tid = threadIdx.x;
    const int qt  = blockIdx.x;
    const int bhi = blockIdx.y;
    const int b   = bhi / HI_;
    const int hi  = bhi % HI_;
    const int h   = hi / I_;

    const float* qbase = q + ((size_t)(b * N_ + qt * 64) * HI_ + hi) * KD_;
    for (int idx = tid; idx < 64 * KD_ / 4; idx += 256) {
        int r = idx >> 5;
        int c = (idx & 31) << 2;
        float4 vv = *(const float4*)(qbase + (size_t)r * HI_ * KD_ + c);
        Qt[(c + 0) * 64 + r] = vv.x;
        Qt[(c + 1) * 64 + r] = vv.y;
        Qt[(c + 2) * 64 + r] = vv.z;
        Qt[(c + 3) * 64 + r] = vv.w;
    }
    if (tid < 64) { mrow[tid] = -1e30f; lrow[tid] = 0.f; }

    float oacc[4][8];
    #pragma unroll
    for (int a = 0; a < 4; a++)
        #pragma unroll
        for (int c = 0; c < 8; c++) oacc[a][c] = 0.f;

    const int sy = tid >> 4;
    const int sx = tid & 15;
    const float scale = 0.088388347648318447f;
    __syncthreads();

    for (int kt = 0; kt <= qt; kt++) {
        const float* kbase = k + ((size_t)(b * N_ + kt * 64) * H_ + h) * KD_;
        const float* vbase = v + ((size_t)(b * N_ + kt * 64) * H_ + h) * VD_;
        for (int idx = tid; idx < 64 * KD_ / 4; idx += 256) {
            int r = idx >> 5;
            int c = (idx & 31) << 2;
            float4 kv4 = *(const float4*)(kbase + (size_t)r * H_ * KD_ + c);
            Kt[(c + 0) * 64 + r] = kv4.x;
            Kt[(c + 1) * 64 + r] = kv4.y;
            Kt[(c + 2) * 64 + r] = kv4.z;
            Kt[(c + 3) * 64 + r] = kv4.w;
            float4 vv4 = *(const float4*)(vbase + (size_t)r * H_ * VD_ + c);
            *(float4*)(Vs + r * VD_ + c) = vv4;
        }
        __syncthreads();

        float sval[4][4];
        #pragma unroll
        for (int a = 0; a < 4; a++)
            #pragma unroll
            for (int bb = 0; bb < 4; bb++) sval[a][bb] = 0.f;

        #pragma unroll 4
        for (int kk = 0; kk < KD_; kk++) {
            float4 qa = *(const float4*)(Qt + kk * 64 + sy * 4);
            float4 kb = *(const float4*)(Kt + kk * 64 + sx * 4);
            float qr[4] = {qa.x, qa.y, qa.z, qa.w};
            float kr[4] = {kb.x, kb.y, kb.z, kb.w};
            #pragma unroll
            for (int a = 0; a < 4; a++)
                #pragma unroll
                for (int bb = 0; bb < 4; bb++)
                    sval[a][bb] = fmaf(qr[a], kr[bb], sval[a][bb]);
        }

        const bool diag = (kt == qt);
        #pragma unroll
        for (int a = 0; a < 4; a++) {
            #pragma unroll
            for (int bb = 0; bb < 4; bb++) {
                float s = sval[a][bb] * scale;
                if (diag && (sx * 4 + bb) > (sy * 4 + a)) s = -1e30f;
                sval[a][bb] = s;
                S[(sy * 4 + a) * 65 + sx * 4 + bb] = s;
            }
        }
        __syncthreads();

        if (tid < 64) {
            float m  = mrow[tid];
            float mx = m;
            #pragma unroll 8
            for (int c = 0; c < 64; c++) mx = fmaxf(mx, S[tid * 65 + c]);
            arow[tid] = __expf(m - mx);
            mrow[tid] = mx;
        }
        __syncthreads();

        #pragma unroll
        for (int a = 0; a < 4; a++) {
            float mx = mrow[sy * 4 + a];
            #pragma unroll
            for (int bb = 0; bb < 4; bb++)
                S[(sy * 4 + a) * 65 + sx * 4 + bb] = __expf(sval[a][bb] - mx);
        }
        __syncthreads();

        if (tid < 64) {
            float sum = 0.f;
            #pragma unroll 8
            for (int c = 0; c < 64; c++) sum += S[tid * 65 + c];
            lrow[tid] = arow[tid] * lrow[tid] + sum;
        }

        #pragma unroll
        for (int a = 0; a < 4; a++) {
            float al = arow[sy * 4 + a];
            #pragma unroll
            for (int c = 0; c < 8; c++) oacc[a][c] *= al;
        }

        #pragma unroll 2
        for (int kk = 0; kk < 64; kk++) {
            float4 v0 = *(const float4*)(Vs + kk * VD_ + sx * 8);
            float4 v1 = *(const float4*)(Vs + kk * VD_ + sx * 8 + 4);
            float vr[8] = {v0.x, v0.y, v0.z, v0.w, v1.x, v1.y, v1.z, v1.w};
            float p[4];
            #pragma unroll
            for (int a = 0; a < 4; a++) p[a] = S[(sy * 4 + a) * 65 + kk];
            #pragma unroll
            for (int a = 0; a < 4; a++)
                #pragma unroll
                for (int c = 0; c < 8; c++)
                    oacc[a][c] = fmaf(p[a], vr[c], oacc[a][c]);
        }
        __syncthreads();
    }

    float* obase = o + ((size_t)(b * N_ + qt * 64) * HI_ + hi) * VD_;
    #pragma unroll
    for (int a = 0; a < 4; a++) {
        float inv = 1.f / lrow[sy * 4 + a];
        float* orow = obase + (size_t)(sy * 4 + a) * HI_ * VD_ + sx * 8;
        *(float4*)(orow)     = make_float4(oacc[a][0] * inv, oacc[a][1] * inv,
                                           oacc[a][2] * inv, oacc[a][3] * inv);
        *(float4*)(orow + 4) = make_float4(oacc[a][4] * inv, oacc[a][5] * inv,
                                           oacc[a][6] * inv, oacc[a][7] * inv);
    }
}

// ---------------------------------------------------------------------------
// Launch
// ---------------------------------------------------------------------------
extern "C" void kernel_launch(void* const* d_in, const int* in_sizes, int n_in,
                              void* d_out, int out_size)
{
    const float* x  = (const float*)d_in[0];   // [2048, 2048]
    const float* Wq = (const float*)d_in[1];   // [2048, 4096]
    const float* Wk = (const float*)d_in[2];   // [2048, 1024]
    const float* Wv = (const float*)d_in[3];   // [2048, 1024]
    const float* Wo = (const float*)d_in[4];   // [4096, 2048]
    float* out = (float*)d_out;                // [2048, 2048]

    float *q, *k, *v, *attn;
    cudaGetSymbolAddress((void**)&q, g_q);
    cudaGetSymbolAddress((void**)&k, g_k);
    cudaGetSymbolAddress((void**)&v, g_v);
    cudaGetSymbolAddress((void**)&attn, g_attn);

    const int M = B_ * N_;   // 2048

    bgemm_kernel<<<dim3(4096 / 128, M / 128), 256>>>(x, Wq, q, M, 4096, D_);
    bgemm_kernel<<<dim3(1024 / 128, M / 128), 256>>>(x, Wk, k, M, 1024, D_);
    bgemm_kernel<<<dim3(1024 / 128, M / 128), 256>>>(x, Wv, v, M, 1024, D_);

    {
        int total_q = B_ * N_ * HI_ * 64;
        rope_kernel<<<(total_q + 255) / 256, 256>>>(q, HI_, total_q);
        int total_k = B_ * N_ * H_ * 64;
        rope_kernel<<<(total_k + 255) / 256, 256>>>(k, H_, total_k);
    }

    cudaFuncSetAttribute(flash_attn_kernel,
                         cudaFuncAttributeMaxDynamicSharedMemorySize,
                         FLASH_SMEM_BYTES);
    flash_attn_kernel<<<dim3(16, 64), 256, FLASH_SMEM_BYTES>>>(q, k, v, attn);

    bgemm_kernel<<<dim3(2048 / 128, M / 128), 256>>>(attn, Wo, out, M, 2048, 4096);
}

// round 3
// speedup vs baseline: 2.4496x; 1.5585x over previous
#include <cuda_runtime.h>
#include <cuda_bf16.h>
#include <math.h>
#include <stdint.h>

// Problem constants
#define B_   2
#define N_   1024
#define D_   2048
#define H_   8
#define I_   4
#define KD_  128
#define VD_  128
#define HI_  32    // H_*I_

// ---------------------------------------------------------------------------
// Device scratch
// ---------------------------------------------------------------------------
__device__ float g_q[(size_t)B_ * N_ * HI_ * KD_];
__device__ float g_k[(size_t)B_ * N_ * H_  * KD_];
__device__ float g_v[(size_t)B_ * N_ * H_  * VD_];
__device__ float g_attn[(size_t)B_ * N_ * HI_ * VD_];
__device__ __nv_bfloat16 g_qh[(size_t)B_ * N_ * HI_ * KD_];
__device__ __nv_bfloat16 g_ql[(size_t)B_ * N_ * HI_ * KD_];
__device__ __nv_bfloat16 g_kh[(size_t)B_ * N_ * H_ * KD_];
__device__ __nv_bfloat16 g_kl[(size_t)B_ * N_ * H_ * KD_];
__device__ __nv_bfloat16 g_vh[(size_t)B_ * N_ * H_ * VD_];
__device__ __nv_bfloat16 g_vl[(size_t)B_ * N_ * H_ * VD_];

// ---------------------------------------------------------------------------
// Tensor-core helpers
// ---------------------------------------------------------------------------
__device__ __forceinline__ void ldsm4(uint32_t* r, const __nv_bfloat16* p) {
    uint32_t a = (uint32_t)__cvta_generic_to_shared(p);
    asm volatile("ldmatrix.sync.aligned.m8n8.x4.shared.b16 {%0,%1,%2,%3}, [%4];"
                 : "=r"(r[0]), "=r"(r[1]), "=r"(r[2]), "=r"(r[3]) : "r"(a));
}
__device__ __forceinline__ void ldsm4t(uint32_t* r, const __nv_bfloat16* p) {
    uint32_t a = (uint32_t)__cvta_generic_to_shared(p);
    asm volatile("ldmatrix.sync.aligned.m8n8.x4.trans.shared.b16 {%0,%1,%2,%3}, [%4];"
                 : "=r"(r[0]), "=r"(r[1]), "=r"(r[2]), "=r"(r[3]) : "r"(a));
}
__device__ __forceinline__ void mma16816(float* c, const uint32_t* a, const uint32_t* b) {
    asm volatile("mma.sync.aligned.m16n8k16.row.col.f32.bf16.bf16.f32 "
                 "{%0,%1,%2,%3}, {%4,%5,%6,%7}, {%8,%9}, {%0,%1,%2,%3};"
                 : "+f"(c[0]), "+f"(c[1]), "+f"(c[2]), "+f"(c[3])
                 : "r"(a[0]), "r"(a[1]), "r"(a[2]), "r"(a[3]),
                   "r"(b[0]), "r"(b[1]));
}
__device__ __forceinline__ uint32_t packbf(float a, float b) {
    __nv_bfloat162 t = __floats2bfloat162_rn(a, b);
    return *(uint32_t*)&t;
}

// ---------------------------------------------------------------------------
// Split-bf16 GEMM (unchanged from round 2)
// ---------------------------------------------------------------------------
#define ASTR 40
#define BSTR 136

__global__ __launch_bounds__(256) void bgemm_kernel(
    const float* __restrict__ A, const float* __restrict__ Bm,
    float* __restrict__ C, int M, int Nc, int Kd)
{
    __shared__ __nv_bfloat16 Ah[128 * ASTR];
    __shared__ __nv_bfloat16 Al[128 * ASTR];
    __shared__ __nv_bfloat16 Bh[32 * BSTR];
    __shared__ __nv_bfloat16 Bl[32 * BSTR];

    const int tid    = threadIdx.x;
    const int lane   = tid & 31;
    const int wid    = tid >> 5;
    const int warp_m = wid & 3;
    const int warp_n = wid >> 2;
    const int brow   = blockIdx.y * 128;
    const int bcol   = blockIdx.x * 128;
    const int lr = lane & 15;
    const int lc = (lane >> 4) << 3;

    float acc[2][8][4];
    #pragma unroll
    for (int im = 0; im < 2; im++)
        #pragma unroll
        for (int jn = 0; jn < 8; jn++)
            #pragma unroll
            for (int t = 0; t < 4; t++) acc[im][jn][t] = 0.f;

    for (int k0 = 0; k0 < Kd; k0 += 32) {
        #pragma unroll
        for (int p = 0; p < 4; p++) {
            int r = p * 32 + (tid >> 3);
            int c = (tid & 7) << 2;
            float4 v = *(const float4*)(A + (size_t)(brow + r) * Kd + k0 + c);
            __nv_bfloat16 h0 = __float2bfloat16(v.x);
            __nv_bfloat16 h1 = __float2bfloat16(v.y);
            __nv_bfloat16 h2 = __float2bfloat16(v.z);
            __nv_bfloat16 h3 = __float2bfloat16(v.w);
            Ah[r * ASTR + c + 0] = h0;
            Ah[r * ASTR + c + 1] = h1;
            Ah[r * ASTR + c + 2] = h2;
            Ah[r * ASTR + c + 3] = h3;
            Al[r * ASTR + c + 0] = __float2bfloat16(v.x - __bfloat162float(h0));
            Al[r * ASTR + c + 1] = __float2bfloat16(v.y - __bfloat162float(h1));
            Al[r * ASTR + c + 2] = __float2bfloat16(v.z - __bfloat162float(h2));
            Al[r * ASTR + c + 3] = __float2bfloat16(v.w - __bfloat162float(h3));
        }
        #pragma unroll
        for (int p = 0; p < 4; p++) {
            int r = p * 8 + (tid >> 5);
            int c = (tid & 31) << 2;
            float4 v = *(const float4*)(Bm + (size_t)(k0 + r) * Nc + bcol + c);
            __nv_bfloat16 h0 = __float2bfloat16(v.x);
            __nv_bfloat16 h1 = __float2bfloat16(v.y);
            __nv_bfloat16 h2 = __float2bfloat16(v.z);
            __nv_bfloat16 h3 = __float2bfloat16(v.w);
            Bh[r * BSTR + c + 0] = h0;
            Bh[r * BSTR + c + 1] = h1;
            Bh[r * BSTR + c + 2] = h2;
            Bh[r * BSTR + c + 3] = h3;
            Bl[r * BSTR + c + 0] = __float2bfloat16(v.x - __bfloat162float(h0));
            Bl[r * BSTR + c + 1] = __float2bfloat16(v.y - __bfloat162float(h1));
            Bl[r * BSTR + c + 2] = __float2bfloat16(v.z - __bfloat162float(h2));
            Bl[r * BSTR + c + 3] = __float2bfloat16(v.w - __bfloat162float(h3));
        }
        __syncthreads();

        #pragma unroll
        for (int ks = 0; ks < 2; ks++) {
            uint32_t ah[2][4], al[2][4];
            #pragma unroll
            for (int im = 0; im < 2; im++) {
                const int ar = (warp_m * 32 + im * 16 + lr) * ASTR + ks * 16 + lc;
                ldsm4(ah[im], &Ah[ar]);
                ldsm4(al[im], &Al[ar]);
            }
            #pragma unroll
            for (int jp = 0; jp < 4; jp++) {
                uint32_t bh[4], bl[4];
                const int boff = (ks * 16 + lr) * BSTR + warp_n * 64 + jp * 16 + lc;
                ldsm4t(bh, &Bh[boff]);
                ldsm4t(bl, &Bl[boff]);
                #pragma unroll
                for (int im = 0; im < 2; im++) {
                    mma16816(acc[im][jp * 2 + 0], ah[im], bh + 0);
                    mma16816(acc[im][jp * 2 + 1], ah[im], bh + 2);
                    mma16816(acc[im][jp * 2 + 0], ah[im], bl + 0);
                    mma16816(acc[im][jp * 2 + 1], ah[im], bl + 2);
                    mma16816(acc[im][jp * 2 + 0], al[im], bh + 0);
                    mma16816(acc[im][jp * 2 + 1], al[im], bh + 2);
                }
            }
        }
        __syncthreads();
    }

    const int r0 = lane >> 2;
    const int c0 = (lane & 3) << 1;
    #pragma unroll
    for (int im = 0; im < 2; im++) {
        #pragma unroll
        for (int jn = 0; jn < 8; jn++) {
            float* cp = C + (size_t)(brow + warp_m * 32 + im * 16 + r0) * Nc
                          + bcol + warp_n * 64 + jn * 8 + c0;
            *(float2*)cp              = make_float2(acc[im][jn][0], acc[im][jn][1]);
            *(float2*)(cp + 8 * (size_t)Nc) = make_float2(acc[im][jn][2], acc[im][jn][3]);
        }
    }
}

// ---------------------------------------------------------------------------
// RoPE + split into bf16 hi/lo (with optional output scale folded in)
// ---------------------------------------------------------------------------
__global__ void rope_split_kernel(const float* __restrict__ in,
                                  __nv_bfloat16* __restrict__ oh,
                                  __nv_bfloat16* __restrict__ ol,
                                  int nheads, int total, float outscale)
{
    int idx = blockIdx.x * blockDim.x + threadIdx.x;
    if (idx >= total) return;
    int j    = idx & 63;
    int t    = idx >> 6;
    int head = t % nheads;
    int row  = t / nheads;
    int n    = row % N_;

    float inv = powf(10000.f, -(float)j * (1.f / 64.f));
    float ang = (float)n * inv;
    float s, c;
    sincosf(ang, &s, &c);

    size_t base = ((size_t)row * nheads + head) * 128;
    float x1 = in[base + j];
    float x2 = in[base + j + 64];
    float r1 = (x1 * c - x2 * s) * outscale;
    float r2 = (x1 * s + x2 * c) * outscale;

    __nv_bfloat16 h1 = __float2bfloat16(r1);
    __nv_bfloat16 h2 = __float2bfloat16(r2);
    oh[base + j]      = h1;
    oh[base + j + 64] = h2;
    ol[base + j]      = __float2bfloat16(r1 - __bfloat162float(h1));
    ol[base + j + 64] = __float2bfloat16(r2 - __bfloat162float(h2));
}

__global__ void split_kernel(const float* __restrict__ in,
                             __nv_bfloat16* __restrict__ oh,
                             __nv_bfloat16* __restrict__ ol, int total)
{
    int idx = blockIdx.x * blockDim.x + threadIdx.x;
    if (idx >= total) return;
    float v = in[idx];
    __nv_bfloat16 h = __float2bfloat16(v);
    oh[idx] = h;
    ol[idx] = __float2bfloat16(v - __bfloat162float(h));
}

// ---------------------------------------------------------------------------
// Tensor-core flash attention. BM=128, BN=64, d=128, causal.
// grid = (8 q-tiles, 64 b*hi), 256 threads (8 warps, 16 rows each).
// Q pre-scaled by (1/sqrt(d))*log2(e); softmax in log2 domain.
// ---------------------------------------------------------------------------
#define QSTR 136
#define KSTR 136
#define VSTR 136
#define FLASH2_SMEM_BYTES ((128*QSTR*2 + 64*KSTR*2 + 64*VSTR*2) * 2)

__global__ __launch_bounds__(256) void flash_mma_kernel(
    const __nv_bfloat16* __restrict__ qh, const __nv_bfloat16* __restrict__ ql,
    const __nv_bfloat16* __restrict__ kh, const __nv_bfloat16* __restrict__ kl,
    const __nv_bfloat16* __restrict__ vh, const __nv_bfloat16* __restrict__ vl,
    float* __restrict__ o)
{
    extern __shared__ __nv_bfloat16 smb[];
    __nv_bfloat16* QH = smb;
    __nv_bfloat16* QL = QH + 128 * QSTR;
    __nv_bfloat16* KH = QL + 128 * QSTR;
    __nv_bfloat16* KL = KH + 64 * KSTR;
    __nv_bfloat16* VH = KL + 64 * KSTR;
    __nv_bfloat16* VL = VH + 64 * VSTR;

    const int tid  = threadIdx.x;
    const int lane = tid & 31;
    const int w    = tid >> 5;
    const int qt   = gridDim.x - 1 - blockIdx.x;   // heavy blocks first
    const int bhi  = blockIdx.y;
    const int b    = bhi >> 5;
    const int hi   = bhi & 31;
    const int h    = hi >> 2;

    const int lr = lane & 15;
    const int lc = (lane >> 4) << 3;

    // Load Q tile (128 x 128, hi+lo)
    const size_t qrow0 = (size_t)(b * N_ + qt * 128) * HI_ + hi;
    for (int i = tid; i < 128 * 16; i += 256) {
        int r = i >> 4, cb = i & 15;
        size_t g = (qrow0 + (size_t)r * HI_) * KD_;
        *(uint4*)(QH + r * QSTR + cb * 8) = *((const uint4*)(qh + g) + cb);
        *(uint4*)(QL + r * QSTR + cb * 8) = *((const uint4*)(ql + g) + cb);
    }

    float m0 = -1e30f, m1 = -1e30f, l0 = 0.f, l1 = 0.f;
    float oacc[16][4];
    #pragma unroll
    for (int nt = 0; nt < 16; nt++)
        #pragma unroll
        for (int t = 0; t < 4; t++) oacc[nt][t] = 0.f;

    const int row0 = qt * 128 + w * 16 + (lane >> 2);   // global q row (and +8)
    const int ktmax = 2 * qt + 1;

    for (int kt = 0; kt <= ktmax; kt++) {
        // Load K/V tiles (64 x 128 each, hi+lo)
        for (int i = tid; i < 64 * 16; i += 256) {
            int r = i >> 4, cb = i & 15;
            size_t g = ((size_t)(b * N_ + kt * 64 + r) * H_ + h) * 128;
            *(uint4*)(KH + r * KSTR + cb * 8) = *((const uint4*)(kh + g) + cb);
            *(uint4*)(KL + r * KSTR + cb * 8) = *((const uint4*)(kl + g) + cb);
            *(uint4*)(VH + r * VSTR + cb * 8) = *((const uint4*)(vh + g) + cb);
            *(uint4*)(VL + r * VSTR + cb * 8) = *((const uint4*)(vl + g) + cb);
        }
        __syncthreads();

        const bool skip = (kt * 64) > (qt * 128 + w * 16 + 15);
        if (!skip) {
            // ---- S = Q K^T (3-pass split) ----
            float sacc[8][4];
            #pragma unroll
            for (int j = 0; j < 8; j++)
                #pragma unroll
                for (int t = 0; t < 4; t++) sacc[j][t] = 0.f;

            #pragma unroll
            for (int ks = 0; ks < 8; ks++) {
                uint32_t ah[4], al[4];
                ldsm4(ah, &QH[(w * 16 + lr) * QSTR + ks * 16 + lc]);
                ldsm4(al, &QL[(w * 16 + lr) * QSTR + ks * 16 + lc]);
                #pragma unroll
                for (int nb = 0; nb < 4; nb++) {
                    uint32_t bhk[4], blk[4];
                    ldsm4(bhk, &KH[(nb * 16 + lr) * KSTR + ks * 16 + lc]);
                    ldsm4(blk, &KL[(nb * 16 + lr) * KSTR + ks * 16 + lc]);
                    uint32_t beh[2] = {bhk[0], bhk[2]};
                    uint32_t boh[2] = {bhk[1], bhk[3]};
                    uint32_t bel[2] = {blk[0], blk[2]};
                    uint32_t bol[2] = {blk[1], blk[3]};
                    mma16816(sacc[2 * nb + 0], ah, beh);
                    mma16816(sacc[2 * nb + 0], al, beh);
                    mma16816(sacc[2 * nb + 0], ah, bel);
                    mma16816(sacc[2 * nb + 1], ah, boh);
                    mma16816(sacc[2 * nb + 1], al, boh);
                    mma16816(sacc[2 * nb + 1], ah, bol);
                }
            }

            // ---- causal mask (only tiles crossing the diagonal) ----
            if (kt >= 2 * qt) {
                #pragma unroll
                for (int j = 0; j < 8; j++) {
                    int col = kt * 64 + j * 8 + 2 * (lane & 3);
                    if (col     > row0)     sacc[j][0] = -1e30f;
                    if (col + 1 > row0)     sacc[j][1] = -1e30f;
                    if (col     > row0 + 8) sacc[j][2] = -1e30f;
                    if (col + 1 > row0 + 8) sacc[j][3] = -1e30f;
                }
            }

            // ---- online softmax (log2 domain) ----
            float tm0 = -1e30f, tm1 = -1e30f;
            #pragma unroll
            for (int j = 0; j < 8; j++) {
                tm0 = fmaxf(tm0, fmaxf(sacc[j][0], sacc[j][1]));
                tm1 = fmaxf(tm1, fmaxf(sacc[j][2], sacc[j][3]));
            }
            tm0 = fmaxf(tm0, __shfl_xor_sync(0xffffffffu, tm0, 1));
            tm0 = fmaxf(tm0, __shfl_xor_sync(0xffffffffu, tm0, 2));
            tm1 = fmaxf(tm1, __shfl_xor_sync(0xffffffffu, tm1, 1));
            tm1 = fmaxf(tm1, __shfl_xor_sync(0xffffffffu, tm1, 2));

            float mn0 = fmaxf(m0, tm0), mn1 = fmaxf(m1, tm1);
            float al0 = exp2f(m0 - mn0), al1 = exp2f(m1 - mn1);
            m0 = mn0; m1 = mn1;

            float rs0 = 0.f, rs1 = 0.f;
            uint32_t pah[4][4], pal[4][4];
            #pragma unroll
            for (int j = 0; j < 8; j++) {
                float p0 = exp2f(sacc[j][0] - mn0);
                float p1 = exp2f(sacc[j][1] - mn0);
                float p2 = exp2f(sacc[j][2] - mn1);
                float p3 = exp2f(sacc[j][3] - mn1);
                rs0 += p0 + p1;
                rs1 += p2 + p3;
                __nv_bfloat16 h0 = __float2bfloat16(p0);
                __nv_bfloat16 h1 = __float2bfloat16(p1);
                __nv_bfloat16 h2 = __float2bfloat16(p2);
                __nv_bfloat16 h3 = __float2bfloat16(p3);
                int kk = j >> 1, odd = j & 1;
                __nv_bfloat162 ph01; ph01.x = h0; ph01.y = h1;
                __nv_bfloat162 ph23; ph23.x = h2; ph23.y = h3;
                pah[kk][odd * 2 + 0] = *(uint32_t*)&ph01;
                pah[kk][odd * 2 + 1] = *(uint32_t*)&ph23;
                pal[kk][odd * 2 + 0] = packbf(p0 - __bfloat162float(h0),
                                              p1 - __bfloat162float(h1));
                pal[kk][odd * 2 + 1] = packbf(p2 - __bfloat162float(h2),
                                              p3 - __bfloat162float(h3));
            }
            rs0 += __shfl_xor_sync(0xffffffffu, rs0, 1);
            rs0 += __shfl_xor_sync(0xffffffffu, rs0, 2);
            rs1 += __shfl_xor_sync(0xffffffffu, rs1, 1);
            rs1 += __shfl_xor_sync(0xffffffffu, rs1, 2);
            l0 = al0 * l0 + rs0;
            l1 = al1 * l1 + rs1;

            #pragma unroll
            for (int nt = 0; nt < 16; nt++) {
                oacc[nt][0] *= al0; oacc[nt][1] *= al0;
                oacc[nt][2] *= al1; oacc[nt][3] *= al1;
            }

            // ---- O += P V (3-pass split) ----
            #pragma unroll
            for (int kk = 0; kk < 4; kk++) {
                #pragma unroll
                for (int jp = 0; jp < 8; jp++) {
                    uint32_t vhr[4], vlr[4];
                    ldsm4t(vhr, &VH[(kk * 16 + lr) * VSTR + jp * 16 + lc]);
                    ldsm4t(vlr, &VL[(kk * 16 + lr) * VSTR + jp * 16 + lc]);
                    mma16816(oacc[2 * jp + 0], pah[kk], vhr + 0);
                    mma16816(oacc[2 * jp + 0], pal[kk], vhr + 0);
                    mma16816(oacc[2 * jp + 0], pah[kk], vlr + 0);
                    mma16816(oacc[2 * jp + 1], pah[kk], vhr + 2);
                    mma16816(oacc[2 * jp + 1], pal[kk], vhr + 2);
                    mma16816(oacc[2 * jp + 1], pah[kk], vlr + 2);
                }
            }
        }
        __syncthreads();
    }

    // ---- epilogue ----
    float inv0 = 1.f / l0, inv1 = 1.f / l1;
    const int c0 = 2 * (lane & 3);
    #pragma unroll
    for (int nt = 0; nt < 16; nt++) {
        size_t r0g = ((size_t)(b * N_ + row0) * HI_ + hi) * VD_ + nt * 8 + c0;
        size_t r1g = ((size_t)(b * N_ + row0 + 8) * HI_ + hi) * VD_ + nt * 8 + c0;
        *(float2*)(o + r0g) = make_float2(oacc[nt][0] * inv0, oacc[nt][1] * inv0);
        *(float2*)(o + r1g) = make_float2(oacc[nt][2] * inv1, oacc[nt][3] * inv1);
    }
}

// ---------------------------------------------------------------------------
// Launch
// ---------------------------------------------------------------------------
extern "C" void kernel_launch(void* const* d_in, const int* in_sizes, int n_in,
                              void* d_out, int out_size)
{
    const float* x  = (const float*)d_in[0];
    const float* Wq = (const float*)d_in[1];
    const float* Wk = (const float*)d_in[2];
    const float* Wv = (const float*)d_in[3];
    const float* Wo = (const float*)d_in[4];
    float* out = (float*)d_out;

    float *q, *k, *v, *attn;
    __nv_bfloat16 *qh, *ql, *kh, *kl, *vh, *vl;
    cudaGetSymbolAddress((void**)&q, g_q);
    cudaGetSymbolAddress((void**)&k, g_k);
    cudaGetSymbolAddress((void**)&v, g_v);
    cudaGetSymbolAddress((void**)&attn, g_attn);
    cudaGetSymbolAddress((void**)&qh, g_qh);
    cudaGetSymbolAddress((void**)&ql, g_ql);
    cudaGetSymbolAddress((void**)&kh, g_kh);
    cudaGetSymbolAddress((void**)&kl, g_kl);
    cudaGetSymbolAddress((void**)&vh, g_vh);
    cudaGetSymbolAddress((void**)&vl, g_vl);

    const int M = B_ * N_;

    bgemm_kernel<<<dim3(4096 / 128, M / 128), 256>>>(x, Wq, q, M, 4096, D_);
    bgemm_kernel<<<dim3(1024 / 128, M / 128), 256>>>(x, Wk, k, M, 1024, D_);
    bgemm_kernel<<<dim3(1024 / 128, M / 128), 256>>>(x, Wv, v, M, 1024, D_);

    // RoPE + convert; fold (1/sqrt(d))*log2(e) into q
    const float s2 = 0.08838834764831845f * 1.4426950408889634f;
    {
        int total_q = B_ * N_ * HI_ * 64;
        rope_split_kernel<<<(total_q + 255) / 256, 256>>>(q, qh, ql, HI_, total_q, s2);
        int total_k = B_ * N_ * H_ * 64;
        rope_split_kernel<<<(total_k + 255) / 256, 256>>>(k, kh, kl, H_, total_k, 1.0f);
        int total_v = B_ * N_ * H_ * VD_;
        split_kernel<<<(total_v + 255) / 256, 256>>>(v, vh, vl, total_v);
    }

    cudaFuncSetAttribute(flash_mma_kernel,
                         cudaFuncAttributeMaxDynamicSharedMemorySize,
                         FLASH2_SMEM_BYTES);
    flash_mma_kernel<<<dim3(8, 64), 256, FLASH2_SMEM_BYTES>>>(
        qh, ql, kh, kl, vh, vl, attn);

    bgemm_kernel<<<dim3(2048 / 128, M / 128), 256>>>(attn, Wo, out, M, 2048, 4096);
}

// round 4
// speedup vs baseline: 3.0250x; 1.2349x over previous
#include <cuda_runtime.h>
#include <cuda_bf16.h>
#include <math.h>
#include <stdint.h>

// Problem constants
#define B_   2
#define N_   1024
#define D_   2048
#define H_   8
#define I_   4
#define KD_  128
#define VD_  128
#define HI_  32    // H_*I_

// ---------------------------------------------------------------------------
// Device scratch
// ---------------------------------------------------------------------------
__device__ float g_q[(size_t)B_ * N_ * HI_ * KD_];
__device__ float g_k[(size_t)B_ * N_ * H_  * KD_];
__device__ float g_v[(size_t)B_ * N_ * H_  * VD_];
// bf16 hi/lo splits
__device__ __nv_bfloat16 g_xh[(size_t)B_ * N_ * D_];
__device__ __nv_bfloat16 g_xl[(size_t)B_ * N_ * D_];
__device__ __nv_bfloat16 g_wqh[(size_t)D_ * HI_ * KD_];
__device__ __nv_bfloat16 g_wql[(size_t)D_ * HI_ * KD_];
__device__ __nv_bfloat16 g_wkh[(size_t)D_ * H_ * KD_];
__device__ __nv_bfloat16 g_wkl[(size_t)D_ * H_ * KD_];
__device__ __nv_bfloat16 g_wvh[(size_t)D_ * H_ * VD_];
__device__ __nv_bfloat16 g_wvl[(size_t)D_ * H_ * VD_];
__device__ __nv_bfloat16 g_woh[(size_t)HI_ * VD_ * D_];
__device__ __nv_bfloat16 g_wol[(size_t)HI_ * VD_ * D_];
__device__ __nv_bfloat16 g_qh[(size_t)B_ * N_ * HI_ * KD_];
__device__ __nv_bfloat16 g_ql[(size_t)B_ * N_ * HI_ * KD_];
__device__ __nv_bfloat16 g_kh[(size_t)B_ * N_ * H_ * KD_];
__device__ __nv_bfloat16 g_kl[(size_t)B_ * N_ * H_ * KD_];
__device__ __nv_bfloat16 g_vh[(size_t)B_ * N_ * H_ * VD_];
__device__ __nv_bfloat16 g_vl[(size_t)B_ * N_ * H_ * VD_];
__device__ __nv_bfloat16 g_ah[(size_t)B_ * N_ * HI_ * VD_];
__device__ __nv_bfloat16 g_al[(size_t)B_ * N_ * HI_ * VD_];

// ---------------------------------------------------------------------------
// Tensor-core + async-copy helpers
// ---------------------------------------------------------------------------
__device__ __forceinline__ void ldsm4(uint32_t* r, const __nv_bfloat16* p) {
    uint32_t a = (uint32_t)__cvta_generic_to_shared(p);
    asm volatile("ldmatrix.sync.aligned.m8n8.x4.shared.b16 {%0,%1,%2,%3}, [%4];"
                 : "=r"(r[0]), "=r"(r[1]), "=r"(r[2]), "=r"(r[3]) : "r"(a));
}
__device__ __forceinline__ void ldsm4t(uint32_t* r, const __nv_bfloat16* p) {
    uint32_t a = (uint32_t)__cvta_generic_to_shared(p);
    asm volatile("ldmatrix.sync.aligned.m8n8.x4.trans.shared.b16 {%0,%1,%2,%3}, [%4];"
                 : "=r"(r[0]), "=r"(r[1]), "=r"(r[2]), "=r"(r[3]) : "r"(a));
}
__device__ __forceinline__ void mma16816(float* c, const uint32_t* a, const uint32_t* b) {
    asm volatile("mma.sync.aligned.m16n8k16.row.col.f32.bf16.bf16.f32 "
                 "{%0,%1,%2,%3}, {%4,%5,%6,%7}, {%8,%9}, {%0,%1,%2,%3};"
                 : "+f"(c[0]), "+f"(c[1]), "+f"(c[2]), "+f"(c[3])
                 : "r"(a[0]), "r"(a[1]), "r"(a[2]), "r"(a[3]),
                   "r"(b[0]), "r"(b[1]));
}
__device__ __forceinline__ uint32_t packbf(float a, float b) {
    __nv_bfloat162 t = __floats2bfloat162_rn(a, b);
    return *(uint32_t*)&t;
}
__device__ __forceinline__ void cp16(void* s, const void* g) {
    uint32_t sa = (uint32_t)__cvta_generic_to_shared(s);
    asm volatile("cp.async.cg.shared.global [%0], [%1], 16;" :: "r"(sa), "l"(g));
}
#define CP_COMMIT() asm volatile("cp.async.commit_group;")
#define CP_WAIT(n)  asm volatile("cp.async.wait_group %0;" :: "n"(n))

// ---------------------------------------------------------------------------
// fp32 -> bf16 hi/lo split (float4 vectorized)
// ---------------------------------------------------------------------------
__global__ void split4_kernel(const float4* __restrict__ in,
                              __nv_bfloat16* __restrict__ oh,
                              __nv_bfloat16* __restrict__ ol, int total4)
{
    int i = blockIdx.x * blockDim.x + threadIdx.x;
    if (i >= total4) return;
    float4 v = in[i];
    __nv_bfloat16 h0 = __float2bfloat16(v.x);
    __nv_bfloat16 h1 = __float2bfloat16(v.y);
    __nv_bfloat16 h2 = __float2bfloat16(v.z);
    __nv_bfloat16 h3 = __float2bfloat16(v.w);
    __nv_bfloat162 hp0; hp0.x = h0; hp0.y = h1;
    __nv_bfloat162 hp1; hp1.x = h2; hp1.y = h3;
    uint2 hw = make_uint2(*(uint32_t*)&hp0, *(uint32_t*)&hp1);
    uint2 lw = make_uint2(packbf(v.x - __bfloat162float(h0), v.y - __bfloat162float(h1)),
                          packbf(v.z - __bfloat162float(h2), v.w - __bfloat162float(h3)));
    *(uint2*)(oh + (size_t)i * 4) = hw;
    *(uint2*)(ol + (size_t)i * 4) = lw;
}

// ---------------------------------------------------------------------------
// Split-bf16 GEMM v2: pre-split operands, cp.async 2-stage pipeline.
// C[M,Nc] = (Ah+Al)*(Bh+Bl) ~ AhBh + AhBl + AlBh, fp32 accum.
// BM=BN=128, BK=32, 256 threads, 8 warps (4m x 2n), warp tile 32x64.
// ---------------------------------------------------------------------------
#define ASTR 40
#define BSTR 136
#define GSTAGE (128*ASTR*2 + 32*BSTR*2)          // bf16 elems per stage
#define GEMM_SMEM_BYTES (GSTAGE * 2 * 2)         // 2 stages * 2 bytes

__global__ __launch_bounds__(256, 1) void bgemm2_kernel(
    const __nv_bfloat16* __restrict__ Ah_g, const __nv_bfloat16* __restrict__ Al_g,
    const __nv_bfloat16* __restrict__ Bh_g, const __nv_bfloat16* __restrict__ Bl_g,
    float* __restrict__ C, int M, int Nc, int Kd)
{
    extern __shared__ __nv_bfloat16 sm[];

    const int tid    = threadIdx.x;
    const int lane   = tid & 31;
    const int wid    = tid >> 5;
    const int warp_m = wid & 3;
    const int warp_n = wid >> 2;
    const int brow   = blockIdx.y * 128;
    const int bcol   = blockIdx.x * 128;
    const int lr = lane & 15;
    const int lc = (lane >> 4) << 3;

    // stage pointers
    __nv_bfloat16* sAh[2]; __nv_bfloat16* sAl[2];
    __nv_bfloat16* sBh[2]; __nv_bfloat16* sBl[2];
    #pragma unroll
    for (int s = 0; s < 2; s++) {
        __nv_bfloat16* base = sm + s * GSTAGE;
        sAh[s] = base;
        sAl[s] = base + 128 * ASTR;
        sBh[s] = base + 128 * ASTR * 2;
        sBl[s] = base + 128 * ASTR * 2 + 32 * BSTR;
    }

    // async load of one K-stage
    auto load_stage = [&](int s, int k0) {
        #pragma unroll
        for (int p = 0; p < 2; p++) {
            int i = p * 256 + tid;           // 0..511
            int r = i >> 2, cc = (i & 3) << 3;
            size_t g = (size_t)(brow + r) * Kd + k0 + cc;
            cp16(sAh[s] + r * ASTR + cc, Ah_g + g);
            cp16(sAl[s] + r * ASTR + cc, Al_g + g);
        }
        #pragma unroll
        for (int p = 0; p < 2; p++) {
            int i = p * 256 + tid;           // 0..511
            int r = i >> 4, cc = (i & 15) << 3;
            size_t g = (size_t)(k0 + r) * Nc + bcol + cc;
            cp16(sBh[s] + r * BSTR + cc, Bh_g + g);
            cp16(sBl[s] + r * BSTR + cc, Bl_g + g);
        }
    };

    float acc[2][8][4];
    #pragma unroll
    for (int im = 0; im < 2; im++)
        #pragma unroll
        for (int jn = 0; jn < 8; jn++)
            #pragma unroll
            for (int t = 0; t < 4; t++) acc[im][jn][t] = 0.f;

    const int nk = Kd >> 5;
    load_stage(0, 0);
    CP_COMMIT();

    for (int kt = 0; kt < nk; kt++) {
        const int s = kt & 1;
        if (kt + 1 < nk) {
            load_stage(s ^ 1, (kt + 1) << 5);
            CP_COMMIT();
            CP_WAIT(1);
        } else {
            CP_WAIT(0);
        }
        __syncthreads();

        #pragma unroll
        for (int ks = 0; ks < 2; ks++) {
            uint32_t ah[2][4], al[2][4];
            #pragma unroll
            for (int im = 0; im < 2; im++) {
                const int ar = (warp_m * 32 + im * 16 + lr) * ASTR + ks * 16 + lc;
                ldsm4(ah[im], sAh[s] + ar);
                ldsm4(al[im], sAl[s] + ar);
            }
            #pragma unroll
            for (int jp = 0; jp < 4; jp++) {
                uint32_t bh[4], bl[4];
                const int boff = (ks * 16 + lr) * BSTR + warp_n * 64 + jp * 16 + lc;
                ldsm4t(bh, sBh[s] + boff);
                ldsm4t(bl, sBl[s] + boff);
                #pragma unroll
                for (int im = 0; im < 2; im++) {
                    mma16816(acc[im][jp * 2 + 0], ah[im], bh + 0);
                    mma16816(acc[im][jp * 2 + 1], ah[im], bh + 2);
                    mma16816(acc[im][jp * 2 + 0], ah[im], bl + 0);
                    mma16816(acc[im][jp * 2 + 1], ah[im], bl + 2);
                    mma16816(acc[im][jp * 2 + 0], al[im], bh + 0);
                    mma16816(acc[im][jp * 2 + 1], al[im], bh + 2);
                }
            }
        }
        __syncthreads();
    }

    const int r0 = lane >> 2;
    const int c0 = (lane & 3) << 1;
    #pragma unroll
    for (int im = 0; im < 2; im++) {
        #pragma unroll
        for (int jn = 0; jn < 8; jn++) {
            float* cp = C + (size_t)(brow + warp_m * 32 + im * 16 + r0) * Nc
                          + bcol + warp_n * 64 + jn * 8 + c0;
            *(float2*)cp              = make_float2(acc[im][jn][0], acc[im][jn][1]);
            *(float2*)(cp + 8 * (size_t)Nc) = make_float2(acc[im][jn][2], acc[im][jn][3]);
        }
    }
}

// ---------------------------------------------------------------------------
// RoPE + split into bf16 hi/lo
// ---------------------------------------------------------------------------
__global__ void rope_split_kernel(const float* __restrict__ in,
                                  __nv_bfloat16* __restrict__ oh,
                                  __nv_bfloat16* __restrict__ ol,
                                  int nheads, int total, float outscale)
{
    int idx = blockIdx.x * blockDim.x + threadIdx.x;
    if (idx >= total) return;
    int j    = idx & 63;
    int t    = idx >> 6;
    int head = t % nheads;
    int row  = t / nheads;
    int n    = row % N_;

    float inv = powf(10000.f, -(float)j * (1.f / 64.f));
    float ang = (float)n * inv;
    float s, c;
    sincosf(ang, &s, &c);

    size_t base = ((size_t)row * nheads + head) * 128;
    float x1 = in[base + j];
    float x2 = in[base + j + 64];
    float r1 = (x1 * c - x2 * s) * outscale;
    float r2 = (x1 * s + x2 * c) * outscale;

    __nv_bfloat16 h1 = __float2bfloat16(r1);
    __nv_bfloat16 h2 = __float2bfloat16(r2);
    oh[base + j]      = h1;
    oh[base + j + 64] = h2;
    ol[base + j]      = __float2bfloat16(r1 - __bfloat162float(h1));
    ol[base + j + 64] = __float2bfloat16(r2 - __bfloat162float(h2));
}

// ---------------------------------------------------------------------------
// Tensor-core flash attention. BM=128, BN=64, d=128, causal.
// Epilogue writes bf16 hi/lo attn directly.
// ---------------------------------------------------------------------------
#define QSTR 136
#define KSTR 136
#define VSTR 136
#define FLASH2_SMEM_BYTES ((128*QSTR*2 + 64*KSTR*2 + 64*VSTR*2) * 2)

__global__ __launch_bounds__(256) void flash_mma_kernel(
    const __nv_bfloat16* __restrict__ qh, const __nv_bfloat16* __restrict__ ql,
    const __nv_bfloat16* __restrict__ kh, const __nv_bfloat16* __restrict__ kl,
    const __nv_bfloat16* __restrict__ vh, const __nv_bfloat16* __restrict__ vl,
    __nv_bfloat16* __restrict__ oh, __nv_bfloat16* __restrict__ ol)
{
    extern __shared__ __nv_bfloat16 smb[];
    __nv_bfloat16* QH = smb;
    __nv_bfloat16* QL = QH + 128 * QSTR;
    __nv_bfloat16* KH = QL + 128 * QSTR;
    __nv_bfloat16* KL = KH + 64 * KSTR;
    __nv_bfloat16* VH = KL + 64 * KSTR;
    __nv_bfloat16* VL = VH + 64 * VSTR;

    const int tid  = threadIdx.x;
    const int lane = tid & 31;
    const int w    = tid >> 5;
    const int qt   = gridDim.x - 1 - blockIdx.x;
    const int bhi  = blockIdx.y;
    const int b    = bhi >> 5;
    const int hi   = bhi & 31;
    const int h    = hi >> 2;

    const int lr = lane & 15;
    const int lc = (lane >> 4) << 3;

    const size_t qrow0 = (size_t)(b * N_ + qt * 128) * HI_ + hi;
    for (int i = tid; i < 128 * 16; i += 256) {
        int r = i >> 4, cb = i & 15;
        size_t g = (qrow0 + (size_t)r * HI_) * KD_;
        *(uint4*)(QH + r * QSTR + cb * 8) = *((const uint4*)(qh + g) + cb);
        *(uint4*)(QL + r * QSTR + cb * 8) = *((const uint4*)(ql + g) + cb);
    }

    float m0 = -1e30f, m1 = -1e30f, l0 = 0.f, l1 = 0.f;
    float oacc[16][4];
    #pragma unroll
    for (int nt = 0; nt < 16; nt++)
        #pragma unroll
        for (int t = 0; t < 4; t++) oacc[nt][t] = 0.f;

    const int row0 = qt * 128 + w * 16 + (lane >> 2);
    const int ktmax = 2 * qt + 1;

    for (int kt = 0; kt <= ktmax; kt++) {
        for (int i = tid; i < 64 * 16; i += 256) {
            int r = i >> 4, cb = i & 15;
            size_t g = ((size_t)(b * N_ + kt * 64 + r) * H_ + h) * 128;
            *(uint4*)(KH + r * KSTR + cb * 8) = *((const uint4*)(kh + g) + cb);
            *(uint4*)(KL + r * KSTR + cb * 8) = *((const uint4*)(kl + g) + cb);
            *(uint4*)(VH + r * VSTR + cb * 8) = *((const uint4*)(vh + g) + cb);
            *(uint4*)(VL + r * VSTR + cb * 8) = *((const uint4*)(vl + g) + cb);
        }
        __syncthreads();

        const bool skip = (kt * 64) > (qt * 128 + w * 16 + 15);
        if (!skip) {
            float sacc[8][4];
            #pragma unroll
            for (int j = 0; j < 8; j++)
                #pragma unroll
                for (int t = 0; t < 4; t++) sacc[j][t] = 0.f;

            #pragma unroll
            for (int ks = 0; ks < 8; ks++) {
                uint32_t ah[4], al[4];
                ldsm4(ah, &QH[(w * 16 + lr) * QSTR + ks * 16 + lc]);
                ldsm4(al, &QL[(w * 16 + lr) * QSTR + ks * 16 + lc]);
                #pragma unroll
                for (int nb = 0; nb < 4; nb++) {
                    uint32_t bhk[4], blk[4];
                    ldsm4(bhk, &KH[(nb * 16 + lr) * KSTR + ks * 16 + lc]);
                    ldsm4(blk, &KL[(nb * 16 + lr) * KSTR + ks * 16 + lc]);
                    uint32_t beh[2] = {bhk[0], bhk[2]};
                    uint32_t boh[2] = {bhk[1], bhk[3]};
                    uint32_t bel[2] = {blk[0], blk[2]};
                    uint32_t bol[2] = {blk[1], blk[3]};
                    mma16816(sacc[2 * nb + 0], ah, beh);
                    mma16816(sacc[2 * nb + 0], al, beh);
                    mma16816(sacc[2 * nb + 0], ah, bel);
                    mma16816(sacc[2 * nb + 1], ah, boh);
                    mma16816(sacc[2 * nb + 1], al, boh);
                    mma16816(sacc[2 * nb + 1], ah, bol);
                }
            }

            if (kt >= 2 * qt) {
                #pragma unroll
                for (int j = 0; j < 8; j++) {
                    int col = kt * 64 + j * 8 + 2 * (lane & 3);
                    if (col     > row0)     sacc[j][0] = -1e30f;
                    if (col + 1 > row0)     sacc[j][1] = -1e30f;
                    if (col     > row0 + 8) sacc[j][2] = -1e30f;
                    if (col + 1 > row0 + 8) sacc[j][3] = -1e30f;
                }
            }

            float tm0 = -1e30f, tm1 = -1e30f;
            #pragma unroll
            for (int j = 0; j < 8; j++) {
                tm0 = fmaxf(tm0, fmaxf(sacc[j][0], sacc[j][1]));
                tm1 = fmaxf(tm1, fmaxf(sacc[j][2], sacc[j][3]));
            }
            tm0 = fmaxf(tm0, __shfl_xor_sync(0xffffffffu, tm0, 1));
            tm0 = fmaxf(tm0, __shfl_xor_sync(0xffffffffu, tm0, 2));
            tm1 = fmaxf(tm1, __shfl_xor_sync(0xffffffffu, tm1, 1));
            tm1 = fmaxf(tm1, __shfl_xor_sync(0xffffffffu, tm1, 2));

            float mn0 = fmaxf(m0, tm0), mn1 = fmaxf(m1, tm1);
            float al0 = exp2f(m0 - mn0), al1 = exp2f(m1 - mn1);
            m0 = mn0; m1 = mn1;

            float rs0 = 0.f, rs1 = 0.f;
            uint32_t pah[4][4], pal[4][4];
            #pragma unroll
            for (int j = 0; j < 8; j++) {
                float p0 = exp2f(sacc[j][0] - mn0);
                float p1 = exp2f(sacc[j][1] - mn0);
                float p2 = exp2f(sacc[j][2] - mn1);
                float p3 = exp2f(sacc[j][3] - mn1);
                rs0 += p0 + p1;
                rs1 += p2 + p3;
                __nv_bfloat16 h0 = __float2bfloat16(p0);
                __nv_bfloat16 h1 = __float2bfloat16(p1);
                __nv_bfloat16 h2 = __float2bfloat16(p2);
                __nv_bfloat16 h3 = __float2bfloat16(p3);
                int kk = j >> 1, odd = j & 1;
                __nv_bfloat162 ph01; ph01.x = h0; ph01.y = h1;
                __nv_bfloat162 ph23; ph23.x = h2; ph23.y = h3;
                pah[kk][odd * 2 + 0] = *(uint32_t*)&ph01;
                pah[kk][odd * 2 + 1] = *(uint32_t*)&ph23;
                pal[kk][odd * 2 + 0] = packbf(p0 - __bfloat162float(h0),
                                              p1 - __bfloat162float(h1));
                pal[kk][odd * 2 + 1] = packbf(p2 - __bfloat162float(h2),
                                              p3 - __bfloat162float(h3));
            }
            rs0 += __shfl_xor_sync(0xffffffffu, rs0, 1);
            rs0 += __shfl_xor_sync(0xffffffffu, rs0, 2);
            rs1 += __shfl_xor_sync(0xffffffffu, rs1, 1);
            rs1 += __shfl_xor_sync(0xffffffffu, rs1, 2);
            l0 = al0 * l0 + rs0;
            l1 = al1 * l1 + rs1;

            #pragma unroll
            for (int nt = 0; nt < 16; nt++) {
                oacc[nt][0] *= al0; oacc[nt][1] *= al0;
                oacc[nt][2] *= al1; oacc[nt][3] *= al1;
            }

            #pragma unroll
            for (int kk = 0; kk < 4; kk++) {
                #pragma unroll
                for (int jp = 0; jp < 8; jp++) {
                    uint32_t vhr[4], vlr[4];
                    ldsm4t(vhr, &VH[(kk * 16 + lr) * VSTR + jp * 16 + lc]);
                    ldsm4t(vlr, &VL[(kk * 16 + lr) * VSTR + jp * 16 + lc]);
                    mma16816(oacc[2 * jp + 0], pah[kk], vhr + 0);
                    mma16816(oacc[2 * jp + 0], pal[kk], vhr + 0);
                    mma16816(oacc[2 * jp + 0], pah[kk], vlr + 0);
                    mma16816(oacc[2 * jp + 1], pah[kk], vhr + 2);
                    mma16816(oacc[2 * jp + 1], pal[kk], vhr + 2);
                    mma16816(oacc[2 * jp + 1], pah[kk], vlr + 2);
                }
            }
        }
        __syncthreads();
    }

    // epilogue: normalized output, split to bf16 hi/lo
    float inv0 = 1.f / l0, inv1 = 1.f / l1;
    const int c0 = 2 * (lane & 3);
    #pragma unroll
    for (int nt = 0; nt < 16; nt++) {
        size_t r0g = ((size_t)(b * N_ + row0) * HI_ + hi) * VD_ + nt * 8 + c0;
        size_t r1g = ((size_t)(b * N_ + row0 + 8) * HI_ + hi) * VD_ + nt * 8 + c0;
        float a0 = oacc[nt][0] * inv0, a1 = oacc[nt][1] * inv0;
        float a2 = oacc[nt][2] * inv1, a3 = oacc[nt][3] * inv1;
        __nv_bfloat16 h0 = __float2bfloat16(a0), h1 = __float2bfloat16(a1);
        __nv_bfloat16 h2 = __float2bfloat16(a2), h3 = __float2bfloat16(a3);
        __nv_bfloat162 hp0; hp0.x = h0; hp0.y = h1;
        __nv_bfloat162 hp1; hp1.x = h2; hp1.y = h3;
        *(uint32_t*)(oh + r0g) = *(uint32_t*)&hp0;
        *(uint32_t*)(ol + r0g) = packbf(a0 - __bfloat162float(h0), a1 - __bfloat162float(h1));
        *(uint32_t*)(oh + r1g) = *(uint32_t*)&hp1;
        *(uint32_t*)(ol + r1g) = packbf(a2 - __bfloat162float(h2), a3 - __bfloat162float(h3));
    }
}

// ---------------------------------------------------------------------------
// Launch
// ---------------------------------------------------------------------------
extern "C" void kernel_launch(void* const* d_in, const int* in_sizes, int n_in,
                              void* d_out, int out_size)
{
    const float* x  = (const float*)d_in[0];
    const float* Wq = (const float*)d_in[1];
    const float* Wk = (const float*)d_in[2];
    const float* Wv = (const float*)d_in[3];
    const float* Wo = (const float*)d_in[4];
    float* out = (float*)d_out;

    float *q, *k, *v;
    __nv_bfloat16 *xh, *xl, *wqh, *wql, *wkh, *wkl, *wvh, *wvl, *woh, *wol;
    __nv_bfloat16 *qh, *ql, *kh, *kl, *vh, *vl, *ah, *al;
    cudaGetSymbolAddress((void**)&q, g_q);
    cudaGetSymbolAddress((void**)&k, g_k);
    cudaGetSymbolAddress((void**)&v, g_v);
    cudaGetSymbolAddress((void**)&xh, g_xh);
    cudaGetSymbolAddress((void**)&xl, g_xl);
    cudaGetSymbolAddress((void**)&wqh, g_wqh);
    cudaGetSymbolAddress((void**)&wql, g_wql);
    cudaGetSymbolAddress((void**)&wkh, g_wkh);
    cudaGetSymbolAddress((void**)&wkl, g_wkl);
    cudaGetSymbolAddress((void**)&wvh, g_wvh);
    cudaGetSymbolAddress((void**)&wvl, g_wvl);
    cudaGetSymbolAddress((void**)&woh, g_woh);
    cudaGetSymbolAddress((void**)&wol, g_wol);
    cudaGetSymbolAddress((void**)&qh, g_qh);
    cudaGetSymbolAddress((void**)&ql, g_ql);
    cudaGetSymbolAddress((void**)&kh, g_kh);
    cudaGetSymbolAddress((void**)&kl, g_kl);
    cudaGetSymbolAddress((void**)&vh, g_vh);
    cudaGetSymbolAddress((void**)&vl, g_vl);
    cudaGetSymbolAddress((void**)&ah, g_ah);
    cudaGetSymbolAddress((void**)&al, g_al);

    const int M = B_ * N_;

    // One-time splits (per call) of inputs and weights
    {
        int t;
        t = B_ * N_ * D_ / 4;
        split4_kernel<<<(t + 255) / 256, 256>>>((const float4*)x, xh, xl, t);
        t = D_ * HI_ * KD_ / 4;
        split4_kernel<<<(t + 255) / 256, 256>>>((const float4*)Wq, wqh, wql, t);
        t = D_ * H_ * KD_ / 4;
        split4_kernel<<<(t + 255) / 256, 256>>>((const float4*)Wk, wkh, wkl, t);
        t = D_ * H_ * VD_ / 4;
        split4_kernel<<<(t + 255) / 256, 256>>>((const float4*)Wv, wvh, wvl, t);
        t = HI_ * VD_ * D_ / 4;
        split4_kernel<<<(t + 255) / 256, 256>>>((const float4*)Wo, woh, wol, t);
    }

    cudaFuncSetAttribute(bgemm2_kernel,
                         cudaFuncAttributeMaxDynamicSharedMemorySize,
                         GEMM_SMEM_BYTES);

    bgemm2_kernel<<<dim3(4096 / 128, M / 128), 256, GEMM_SMEM_BYTES>>>(
        xh, xl, wqh, wql, q, M, 4096, D_);
    bgemm2_kernel<<<dim3(1024 / 128, M / 128), 256, GEMM_SMEM_BYTES>>>(
        xh, xl, wkh, wkl, k, M, 1024, D_);
    bgemm2_kernel<<<dim3(1024 / 128, M / 128), 256, GEMM_SMEM_BYTES>>>(
        xh, xl, wvh, wvl, v, M, 1024, D_);

    // RoPE + convert; fold (1/sqrt(d))*log2(e) into q
    const float s2 = 0.08838834764831845f * 1.4426950408889634f;
    {
        int total_q = B_ * N_ * HI_ * 64;
        rope_split_kernel<<<(total_q + 255) / 256, 256>>>(q, qh, ql, HI_, total_q, s2);
        int total_k = B_ * N_ * H_ * 64;
        rope_split_kernel<<<(total_k + 255) / 256, 256>>>(k, kh, kl, H_, total_k, 1.0f);
        int total_v4 = B_ * N_ * H_ * VD_ / 4;
        split4_kernel<<<(total_v4 + 255) / 256, 256>>>((const float4*)v, vh, vl, total_v4);
    }

    cudaFuncSetAttribute(flash_mma_kernel,
                         cudaFuncAttributeMaxDynamicSharedMemorySize,
                         FLASH2_SMEM_BYTES);
    flash_mma_kernel<<<dim3(8, 64), 256, FLASH2_SMEM_BYTES>>>(
        qh, ql, kh, kl, vh, vl, ah, al);

    bgemm2_kernel<<<dim3(2048 / 128, M / 128), 256, GEMM_SMEM_BYTES>>>(
        ah, al, woh, wol, out, M, 2048, 4096);
}

// round 6
// speedup vs baseline: 3.1229x; 1.0324x over previous
#include <cuda_runtime.h>
#include <cuda_bf16.h>
#include <math.h>
#include <stdint.h>

// Problem constants
#define B_   2
#define N_   1024
#define D_   2048
#define H_   8
#define I_   4
#define KD_  128
#define VD_  128
#define HI_  32    // H_*I_
#define QKV_W 6144  // 4096 q + 1024 k + 1024 v

// ---------------------------------------------------------------------------
// Device scratch
// ---------------------------------------------------------------------------
__device__ float g_qkv[(size_t)B_ * N_ * QKV_W];          // fused q|k|v fp32
__device__ __nv_bfloat16 g_xh[(size_t)B_ * N_ * D_];
__device__ __nv_bfloat16 g_xl[(size_t)B_ * N_ * D_];
__device__ __nv_bfloat16 g_wallh[(size_t)D_ * QKV_W];     // fused Wq|Wk|Wv
__device__ __nv_bfloat16 g_walll[(size_t)D_ * QKV_W];
__device__ __nv_bfloat16 g_woh[(size_t)HI_ * VD_ * D_];
__device__ __nv_bfloat16 g_wol[(size_t)HI_ * VD_ * D_];
__device__ __nv_bfloat16 g_qh[(size_t)B_ * N_ * HI_ * KD_];
__device__ __nv_bfloat16 g_ql[(size_t)B_ * N_ * HI_ * KD_];
__device__ __nv_bfloat16 g_kh[(size_t)B_ * N_ * H_ * KD_];
__device__ __nv_bfloat16 g_kl[(size_t)B_ * N_ * H_ * KD_];
__device__ __nv_bfloat16 g_vh[(size_t)B_ * N_ * H_ * VD_];
__device__ __nv_bfloat16 g_vl[(size_t)B_ * N_ * H_ * VD_];
__device__ __nv_bfloat16 g_ah[(size_t)B_ * N_ * HI_ * VD_];
__device__ __nv_bfloat16 g_al[(size_t)B_ * N_ * HI_ * VD_];

// ---------------------------------------------------------------------------
// Helpers
// ---------------------------------------------------------------------------
__device__ __forceinline__ void ldsm4(uint32_t* r, const __nv_bfloat16* p) {
    uint32_t a = (uint32_t)__cvta_generic_to_shared(p);
    asm volatile("ldmatrix.sync.aligned.m8n8.x4.shared.b16 {%0,%1,%2,%3}, [%4];"
                 : "=r"(r[0]), "=r"(r[1]), "=r"(r[2]), "=r"(r[3]) : "r"(a));
}
__device__ __forceinline__ void ldsm4t(uint32_t* r, const __nv_bfloat16* p) {
    uint32_t a = (uint32_t)__cvta_generic_to_shared(p);
    asm volatile("ldmatrix.sync.aligned.m8n8.x4.trans.shared.b16 {%0,%1,%2,%3}, [%4];"
                 : "=r"(r[0]), "=r"(r[1]), "=r"(r[2]), "=r"(r[3]) : "r"(a));
}
__device__ __forceinline__ void mma16816(float* c, const uint32_t* a, const uint32_t* b) {
    asm volatile("mma.sync.aligned.m16n8k16.row.col.f32.bf16.bf16.f32 "
                 "{%0,%1,%2,%3}, {%4,%5,%6,%7}, {%8,%9}, {%0,%1,%2,%3};"
                 : "+f"(c[0]), "+f"(c[1]), "+f"(c[2]), "+f"(c[3])
                 : "r"(a[0]), "r"(a[1]), "r"(a[2]), "r"(a[3]),
                   "r"(b[0]), "r"(b[1]));
}
__device__ __forceinline__ uint32_t packbf(float a, float b) {
    __nv_bfloat162 t = __floats2bfloat162_rn(a, b);
    return *(uint32_t*)&t;
}
__device__ __forceinline__ void cp16s(uint32_t s, const void* g) {
    asm volatile("cp.async.cg.shared.global [%0], [%1], 16;" :: "r"(s), "l"(g));
}
#define CP_COMMIT() asm volatile("cp.async.commit_group;" ::: "memory")
#define CP_WAIT(n)  asm volatile("cp.async.wait_group %0;" :: "n"(n) : "memory")

// ---------------------------------------------------------------------------
// fp32 -> bf16 hi/lo split (float4 vectorized)
// ---------------------------------------------------------------------------
__global__ void split4_kernel(const float4* __restrict__ in,
                              __nv_bfloat16* __restrict__ oh,
                              __nv_bfloat16* __restrict__ ol, int total4)
{
    int i = blockIdx.x * blockDim.x + threadIdx.x;
    if (i >= total4) return;
    float4 v = in[i];
    __nv_bfloat16 h0 = __float2bfloat16(v.x);
    __nv_bfloat16 h1 = __float2bfloat16(v.y);
    __nv_bfloat16 h2 = __float2bfloat16(v.z);
    __nv_bfloat16 h3 = __float2bfloat16(v.w);
    __nv_bfloat162 hp0; hp0.x = h0; hp0.y = h1;
    __nv_bfloat162 hp1; hp1.x = h2; hp1.y = h3;
    uint2 hw = make_uint2(*(uint32_t*)&hp0, *(uint32_t*)&hp1);
    uint2 lw = make_uint2(packbf(v.x - __bfloat162float(h0), v.y - __bfloat162float(h1)),
                          packbf(v.z - __bfloat162float(h2), v.w - __bfloat162float(h3)));
    *(uint2*)(oh + (size_t)i * 4) = hw;
    *(uint2*)(ol + (size_t)i * 4) = lw;
}

// Split + place into a wider fused matrix at column offset
__global__ void splitcat4_kernel(const float* __restrict__ in,
                                 __nv_bfloat16* __restrict__ oh,
                                 __nv_bfloat16* __restrict__ ol,
                                 int srcW, int dstW, int colofs, int total4)
{
    int i = blockIdx.x * blockDim.x + threadIdx.x;
    if (i >= total4) return;
    int w4  = srcW >> 2;
    int row = i / w4;
    int c4  = i - row * w4;
    float4 v = *(const float4*)(in + (size_t)row * srcW + c4 * 4);
    size_t o = (size_t)row * dstW + colofs + c4 * 4;
    __nv_bfloat16 h0 = __float2bfloat16(v.x);
    __nv_bfloat16 h1 = __float2bfloat16(v.y);
    __nv_bfloat16 h2 = __float2bfloat16(v.z);
    __nv_bfloat16 h3 = __float2bfloat16(v.w);
    __nv_bfloat162 hp0; hp0.x = h0; hp0.y = h1;
    __nv_bfloat162 hp1; hp1.x = h2; hp1.y = h3;
    *(uint2*)(oh + o) = make_uint2(*(uint32_t*)&hp0, *(uint32_t*)&hp1);
    *(uint2*)(ol + o) = make_uint2(
        packbf(v.x - __bfloat162float(h0), v.y - __bfloat162float(h1)),
        packbf(v.z - __bfloat162float(h2), v.w - __bfloat162float(h3)));
}

// ---------------------------------------------------------------------------
// Split-bf16 GEMM, 3-stage cp.async pipeline.
// C[M,Nc] = (Ah+Al)*(Bh+Bl) ~ AhBh + AhBl + AlBh, fp32 accum.
// BM=BN=128, BK=32, 256 threads, 8 warps (4m x 2n), warp tile 32x64.
// ---------------------------------------------------------------------------
#define ASTR 40
#define BSTR 136
#define GSTAGE (128*ASTR*2 + 32*BSTR*2)          // bf16 elems per stage (18944)
#define GEMM_SMEM_BYTES (GSTAGE * 3 * 2)         // 3 stages

__global__ __launch_bounds__(256, 1) void bgemm3_kernel(
    const __nv_bfloat16* __restrict__ Ah_g, const __nv_bfloat16* __restrict__ Al_g,
    const __nv_bfloat16* __restrict__ Bh_g, const __nv_bfloat16* __restrict__ Bl_g,
    float* __restrict__ C, int M, int Nc, int Kd)
{
    extern __shared__ __nv_bfloat16 sm[];

    const int tid    = threadIdx.x;
    const int lane   = tid & 31;
    const int wid    = tid >> 5;
    const int warp_m = wid & 3;
    const int warp_n = wid >> 2;
    const int brow   = blockIdx.y * 128;
    const int bcol   = blockIdx.x * 128;
    const int lr = lane & 15;
    const int lc = (lane >> 4) << 3;

    __nv_bfloat16* sAh[3]; __nv_bfloat16* sAl[3];
    __nv_bfloat16* sBh[3]; __nv_bfloat16* sBl[3];
    #pragma unroll
    for (int s = 0; s < 3; s++) {
        __nv_bfloat16* base = sm + s * GSTAGE;
        sAh[s] = base;
        sAl[s] = base + 128 * ASTR;
        sBh[s] = base + 128 * ASTR * 2;
        sBl[s] = base + 128 * ASTR * 2 + 32 * BSTR;
    }

    auto load_stage = [&](int s, int k0) {
        #pragma unroll
        for (int p = 0; p < 2; p++) {
            int i = p * 256 + tid;           // 0..511
            int r = i >> 2, cc = (i & 3) << 3;
            size_t g = (size_t)(brow + r) * Kd + k0 + cc;
            uint32_t sa = (uint32_t)__cvta_generic_to_shared(sAh[s] + r * ASTR + cc);
            uint32_t sl = (uint32_t)__cvta_generic_to_shared(sAl[s] + r * ASTR + cc);
            cp16s(sa, Ah_g + g);
            cp16s(sl, Al_g + g);
        }
        #pragma unroll
        for (int p = 0; p < 2; p++) {
            int i = p * 256 + tid;           // 0..511
            int r = i >> 4, cc = (i & 15) << 3;
            size_t g = (size_t)(k0 + r) * Nc + bcol + cc;
            uint32_t sh = (uint32_t)__cvta_generic_to_shared(sBh[s] + r * BSTR + cc);
            uint32_t sl = (uint32_t)__cvta_generic_to_shared(sBl[s] + r * BSTR + cc);
            cp16s(sh, Bh_g + g);
            cp16s(sl, Bl_g + g);
        }
    };

    float acc[2][8][4];
    #pragma unroll
    for (int im = 0; im < 2; im++)
        #pragma unroll
        for (int jn = 0; jn < 8; jn++)
            #pragma unroll
            for (int t = 0; t < 4; t++) acc[im][jn][t] = 0.f;

    const int nk = Kd >> 5;
    load_stage(0, 0);
    CP_COMMIT();
    load_stage(1, 32);
    CP_COMMIT();

    for (int kt = 0; kt < nk; kt++) {
        const int s = kt % 3;
        CP_WAIT(1);
        __syncthreads();
        if (kt + 2 < nk) {
            load_stage((kt + 2) % 3, (kt + 2) << 5);
            CP_COMMIT();
        }

        #pragma unroll
        for (int ks = 0; ks < 2; ks++) {
            uint32_t ah[2][4], al[2][4];
            #pragma unroll
            for (int im = 0; im < 2; im++) {
                const int ar = (warp_m * 32 + im * 16 + lr) * ASTR + ks * 16 + lc;
                ldsm4(ah[im], sAh[s] + ar);
                ldsm4(al[im], sAl[s] + ar);
            }
            #pragma unroll
            for (int jp = 0; jp < 4; jp++) {
                uint32_t bh[4], bl[4];
                const int boff = (ks * 16 + lr) * BSTR + warp_n * 64 + jp * 16 + lc;
                ldsm4t(bh, sBh[s] + boff);
                ldsm4t(bl, sBl[s] + boff);
                #pragma unroll
                for (int im = 0; im < 2; im++) {
                    mma16816(acc[im][jp * 2 + 0], ah[im], bh + 0);
                    mma16816(acc[im][jp * 2 + 1], ah[im], bh + 2);
                    mma16816(acc[im][jp * 2 + 0], ah[im], bl + 0);
                    mma16816(acc[im][jp * 2 + 1], ah[im], bl + 2);
                    mma16816(acc[im][jp * 2 + 0], al[im], bh + 0);
                    mma16816(acc[im][jp * 2 + 1], al[im], bh + 2);
                }
            }
        }
    }

    const int r0 = lane >> 2;
    const int c0 = (lane & 3) << 1;
    #pragma unroll
    for (int im = 0; im < 2; im++) {
        #pragma unroll
        for (int jn = 0; jn < 8; jn++) {
            float* cp = C + (size_t)(brow + warp_m * 32 + im * 16 + r0) * Nc
                          + bcol + warp_n * 64 + jn * 8 + c0;
            *(float2*)cp              = make_float2(acc[im][jn][0], acc[im][jn][1]);
            *(float2*)(cp + 8 * (size_t)Nc) = make_float2(acc[im][jn][2], acc[im][jn][3]);
        }
    }
}

// ---------------------------------------------------------------------------
// RoPE + split into bf16 hi/lo (reads from fused qkv buffer)
// ---------------------------------------------------------------------------
__global__ void rope_split_kernel(const float* __restrict__ in,
                                  __nv_bfloat16* __restrict__ oh,
                                  __nv_bfloat16* __restrict__ ol,
                                  int nheads, int total, float outscale,
                                  int rowstride, int colofs)
{
    int idx = blockIdx.x * blockDim.x + threadIdx.x;
    if (idx >= total) return;
    int j    = idx & 63;
    int t    = idx >> 6;
    int head = t % nheads;
    int row  = t / nheads;
    int n    = row % N_;

    float inv = powf(10000.f, -(float)j * (1.f / 64.f));
    float ang = (float)n * inv;
    float s, c;
    sincosf(ang, &s, &c);

    const float* p = in + (size_t)row * rowstride + colofs + head * 128;
    float x1 = p[j];
    float x2 = p[j + 64];
    float r1 = (x1 * c - x2 * s) * outscale;
    float r2 = (x1 * s + x2 * c) * outscale;

    size_t ob = ((size_t)row * nheads + head) * 128;
    __nv_bfloat16 h1 = __float2bfloat16(r1);
    __nv_bfloat16 h2 = __float2bfloat16(r2);
    oh[ob + j]      = h1;
    oh[ob + j + 64] = h2;
    ol[ob + j]      = __float2bfloat16(r1 - __bfloat162float(h1));
    ol[ob + j + 64] = __float2bfloat16(r2 - __bfloat162float(h2));
}

// v split out of fused buffer
__global__ void vsplit_kernel(const float* __restrict__ qkv,
                              __nv_bfloat16* __restrict__ oh,
                              __nv_bfloat16* __restrict__ ol, int total4)
{
    int i = blockIdx.x * blockDim.x + threadIdx.x;
    if (i >= total4) return;
    int row = i >> 8;
    int c4  = i & 255;
    float4 v = *(const float4*)(qkv + (size_t)row * QKV_W + 5120 + c4 * 4);
    size_t o = (size_t)row * 1024 + c4 * 4;
    __nv_bfloat16 h0 = __float2bfloat16(v.x);
    __nv_bfloat16 h1 = __float2bfloat16(v.y);
    __nv_bfloat16 h2 = __float2bfloat16(v.z);
    __nv_bfloat16 h3 = __float2bfloat16(v.w);
    __nv_bfloat162 hp0; hp0.x = h0; hp0.y = h1;
    __nv_bfloat162 hp1; hp1.x = h2; hp1.y = h3;
    *(uint2*)(oh + o) = make_uint2(*(uint32_t*)&hp0, *(uint32_t*)&hp1);
    *(uint2*)(ol + o) = make_uint2(
        packbf(v.x - __bfloat162float(h0), v.y - __bfloat162float(h1)),
        packbf(v.z - __bfloat162float(h2), v.w - __bfloat162float(h3)));
}

// ---------------------------------------------------------------------------
// Tensor-core flash attention (HMMA). BM=128, BN=64, d=128, causal.
// K/V double-buffered via cp.async.
// ---------------------------------------------------------------------------
#define QSTR 136
#define KSTR 136
#define VSTR 136
#define KVSTG (4 * 64 * 136)                       // bf16 elems per KV stage
#define FLASH3_SMEM_BYTES ((2*128*QSTR + 2*KVSTG) * 2)

__global__ __launch_bounds__(256) void flash_mma_kernel(
    const __nv_bfloat16* __restrict__ qh, const __nv_bfloat16* __restrict__ ql,
    const __nv_bfloat16* __restrict__ kh, const __nv_bfloat16* __restrict__ kl,
    const __nv_bfloat16* __restrict__ vh, const __nv_bfloat16* __restrict__ vl,
    __nv_bfloat16* __restrict__ oh, __nv_bfloat16* __restrict__ ol)
{
    extern __shared__ __nv_bfloat16 smb[];
    __nv_bfloat16* QH  = smb;
    __nv_bfloat16* QL  = QH + 128 * QSTR;
    __nv_bfloat16* KV0 = QL + 128 * QSTR;

    const int tid  = threadIdx.x;
    const int lane = tid & 31;
    const int w    = tid >> 5;
    const int qt   = gridDim.x - 1 - blockIdx.x;
    const int bhi  = blockIdx.y;
    const int b    = bhi >> 5;
    const int hi   = bhi & 31;
    const int h    = hi >> 2;

    const int lr = lane & 15;
    const int lc = (lane >> 4) << 3;
    const uint32_t kvu = (uint32_t)__cvta_generic_to_shared(KV0);

    // KV stage sub-offsets in bytes
    const uint32_t KLOFS = 64 * 136 * 2;       // 17408
    const uint32_t VHOFS = 2 * KLOFS;
    const uint32_t VLOFS = 3 * KLOFS;
    const uint32_t KVSTB = 4 * KLOFS;          // 69632

    auto load_kv = [&](int s, int kt) {
        #pragma unroll
        for (int p = 0; p < 4; p++) {
            int i = p * 256 + tid;             // 0..1023
            int r = i >> 4, cb = (i & 15) << 4;
            size_t g = ((size_t)(b * N_ + kt * 64 + r) * H_ + h) * 128 + (cb >> 1);
            uint32_t bs = kvu + s * KVSTB + r * 272 + cb;
            cp16s(bs, kh + g);
            cp16s(bs + KLOFS, kl + g);
            cp16s(bs + VHOFS, vh + g);
            cp16s(bs + VLOFS, vl + g);
        }
    };

    // Load Q tile (sync loads)
    const size_t qrow0 = (size_t)(b * N_ + qt * 128) * HI_ + hi;
    for (int i = tid; i < 128 * 16; i += 256) {
        int r = i >> 4, cb = i & 15;
        size_t g = (qrow0 + (size_t)r * HI_) * KD_;
        *(uint4*)(QH + r * QSTR + cb * 8) = *((const uint4*)(qh + g) + cb);
        *(uint4*)(QL + r * QSTR + cb * 8) = *((const uint4*)(ql + g) + cb);
    }

    float m0 = -1e30f, m1 = -1e30f, l0 = 0.f, l1 = 0.f;
    float oacc[16][4];
    #pragma unroll
    for (int nt = 0; nt < 16; nt++)
        #pragma unroll
        for (int t = 0; t < 4; t++) oacc[nt][t] = 0.f;

    const int row0 = qt * 128 + w * 16 + (lane >> 2);
    const int ktmax = 2 * qt + 1;

    load_kv(0, 0);
    CP_COMMIT();

    for (int kt = 0; kt <= ktmax; kt++) {
        const int s = kt & 1;
        if (kt < ktmax) {
            load_kv(s ^ 1, kt + 1);
            CP_COMMIT();
            CP_WAIT(1);
        } else {
            CP_WAIT(0);
        }
        __syncthreads();

        __nv_bfloat16* KH = KV0 + s * KVSTG;
        __nv_bfloat16* KL = KH + 64 * 136;
        __nv_bfloat16* VH = KL + 64 * 136;
        __nv_bfloat16* VL = VH + 64 * 136;

        const bool skip = (kt * 64) > (qt * 128 + w * 16 + 15);
        if (!skip) {
            float sacc[8][4];
            #pragma unroll
            for (int j = 0; j < 8; j++)
                #pragma unroll
                for (int t = 0; t < 4; t++) sacc[j][t] = 0.f;

            #pragma unroll
            for (int ks = 0; ks < 8; ks++) {
                uint32_t ah[4], al[4];
                ldsm4(ah, &QH[(w * 16 + lr) * QSTR + ks * 16 + lc]);
                ldsm4(al, &QL[(w * 16 + lr) * QSTR + ks * 16 + lc]);
                #pragma unroll
                for (int nb = 0; nb < 4; nb++) {
                    uint32_t bhk[4], blk[4];
                    ldsm4(bhk, &KH[(nb * 16 + lr) * KSTR + ks * 16 + lc]);
                    ldsm4(blk, &KL[(nb * 16 + lr) * KSTR + ks * 16 + lc]);
                    uint32_t beh[2] = {bhk[0], bhk[2]};
                    uint32_t boh[2] = {bhk[1], bhk[3]};
                    uint32_t bel[2] = {blk[0], blk[2]};
                    uint32_t bol[2] = {blk[1], blk[3]};
                    mma16816(sacc[2 * nb + 0], ah, beh);
                    mma16816(sacc[2 * nb + 0], al, beh);
                    mma16816(sacc[2 * nb + 0], ah, bel);
                    mma16816(sacc[2 * nb + 1], ah, boh);
                    mma16816(sacc[2 * nb + 1], al, boh);
                    mma16816(sacc[2 * nb + 1], ah, bol);
                }
            }

            if (kt >= 2 * qt) {
                #pragma unroll
                for (int j = 0; j < 8; j++) {
                    int col = kt * 64 + j * 8 + 2 * (lane & 3);
                    if (col     > row0)     sacc[j][0] = -1e30f;
                    if (col + 1 > row0)     sacc[j][1] = -1e30f;
                    if (col     > row0 + 8) sacc[j][2] = -1e30f;
                    if (col + 1 > row0 + 8) sacc[j][3] = -1e30f;
                }
            }

            float tm0 = -1e30f, tm1 = -1e30f;
            #pragma unroll
            for (int j = 0; j < 8; j++) {
                tm0 = fmaxf(tm0, fmaxf(sacc[j][0], sacc[j][1]));
                tm1 = fmaxf(tm1, fmaxf(sacc[j][2], sacc[j][3]));
            }
            tm0 = fmaxf(tm0, __shfl_xor_sync(0xffffffffu, tm0, 1));
            tm0 = fmaxf(tm0, __shfl_xor_sync(0xffffffffu, tm0, 2));
            tm1 = fmaxf(tm1, __shfl_xor_sync(0xffffffffu, tm1, 1));
            tm1 = fmaxf(tm1, __shfl_xor_sync(0xffffffffu, tm1, 2));

            float mn0 = fmaxf(m0, tm0), mn1 = fmaxf(m1, tm1);
            float al0 = exp2f(m0 - mn0), al1 = exp2f(m1 - mn1);
            m0 = mn0; m1 = mn1;

            float rs0 = 0.f, rs1 = 0.f;
            uint32_t pah[4][4], pal[4][4];
            #pragma unroll
            for (int j = 0; j < 8; j++) {
                float p0 = exp2f(sacc[j][0] - mn0);
                float p1 = exp2f(sacc[j][1] - mn0);
                float p2 = exp2f(sacc[j][2] - mn1);
                float p3 = exp2f(sacc[j][3] - mn1);
                rs0 += p0 + p1;
                rs1 += p2 + p3;
                __nv_bfloat16 h0 = __float2bfloat16(p0);
                __nv_bfloat16 h1 = __float2bfloat16(p1);
                __nv_bfloat16 h2 = __float2bfloat16(p2);
                __nv_bfloat16 h3 = __float2bfloat16(p3);
                int kk = j >> 1, odd = j & 1;
                __nv_bfloat162 ph01; ph01.x = h0; ph01.y = h1;
                __nv_bfloat162 ph23; ph23.x = h2; ph23.y = h3;
                pah[kk][odd * 2 + 0] = *(uint32_t*)&ph01;
                pah[kk][odd * 2 + 1] = *(uint32_t*)&ph23;
                pal[kk][odd * 2 + 0] = packbf(p0 - __bfloat162float(h0),
                                              p1 - __bfloat162float(h1));
                pal[kk][odd * 2 + 1] = packbf(p2 - __bfloat162float(h2),
                                              p3 - __bfloat162float(h3));
            }
            rs0 += __shfl_xor_sync(0xffffffffu, rs0, 1);
            rs0 += __shfl_xor_sync(0xffffffffu, rs0, 2);
            rs1 += __shfl_xor_sync(0xffffffffu, rs1, 1);
            rs1 += __shfl_xor_sync(0xffffffffu, rs1, 2);
            l0 = al0 * l0 + rs0;
            l1 = al1 * l1 + rs1;

            #pragma unroll
            for (int nt = 0; nt < 16; nt++) {
                oacc[nt][0] *= al0; oacc[nt][1] *= al0;
                oacc[nt][2] *= al1; oacc[nt][3] *= al1;
            }

            #pragma unroll
            for (int kk = 0; kk < 4; kk++) {
                #pragma unroll
                for (int jp = 0; jp < 8; jp++) {
                    uint32_t vhr[4], vlr[4];
                    ldsm4t(vhr, &VH[(kk * 16 + lr) * VSTR + jp * 16 + lc]);
                    ldsm4t(vlr, &VL[(kk * 16 + lr) * VSTR + jp * 16 + lc]);
                    mma16816(oacc[2 * jp + 0], pah[kk], vhr + 0);
                    mma16816(oacc[2 * jp + 0], pal[kk], vhr + 0);
                    mma16816(oacc[2 * jp + 0], pah[kk], vlr + 0);
                    mma16816(oacc[2 * jp + 1], pah[kk], vhr + 2);
                    mma16816(oacc[2 * jp + 1], pal[kk], vhr + 2);
                    mma16816(oacc[2 * jp + 1], pah[kk], vlr + 2);
                }
            }
        }
        __syncthreads();
    }

    float inv0 = 1.f / l0, inv1 = 1.f / l1;
    const int c0 = 2 * (lane & 3);
    #pragma unroll
    for (int nt = 0; nt < 16; nt++) {
        size_t r0g = ((size_t)(b * N_ + row0) * HI_ + hi) * VD_ + nt * 8 + c0;
        size_t r1g = ((size_t)(b * N_ + row0 + 8) * HI_ + hi) * VD_ + nt * 8 + c0;
        float a0 = oacc[nt][0] * inv0, a1 = oacc[nt][1] * inv0;
        float a2 = oacc[nt][2] * inv1, a3 = oacc[nt][3] * inv1;
        __nv_bfloat16 h0 = __float2bfloat16(a0), h1 = __float2bfloat16(a1);
        __nv_bfloat16 h2 = __float2bfloat16(a2), h3 = __float2bfloat16(a3);
        __nv_bfloat162 hp0; hp0.x = h0; hp0.y = h1;
        __nv_bfloat162 hp1; hp1.x = h2; hp1.y = h3;
        *(uint32_t*)(oh + r0g) = *(uint32_t*)&hp0;
        *(uint32_t*)(ol + r0g) = packbf(a0 - __bfloat162float(h0), a1 - __bfloat162float(h1));
        *(uint32_t*)(oh + r1g) = *(uint32_t*)&hp1;
        *(uint32_t*)(ol + r1g) = packbf(a2 - __bfloat162float(h2), a3 - __bfloat162float(h3));
    }
}

// ---------------------------------------------------------------------------
// Launch
// ---------------------------------------------------------------------------
extern "C" void kernel_launch(void* const* d_in, const int* in_sizes, int n_in,
                              void* d_out, int out_size)
{
    const float* x  = (const float*)d_in[0];
    const float* Wq = (const float*)d_in[1];   // [2048, 4096]
    const float* Wk = (const float*)d_in[2];   // [2048, 1024]
    const float* Wv = (const float*)d_in[3];   // [2048, 1024]
    const float* Wo = (const float*)d_in[4];   // [4096, 2048]
    float* out = (float*)d_out;

    float* qkv;
    __nv_bfloat16 *xh, *xl, *wallh, *walll, *woh, *wol;
    __nv_bfloat16 *qh, *ql, *kh, *kl, *vh, *vl, *ah, *al;
    cudaGetSymbolAddress((void**)&qkv, g_qkv);
    cudaGetSymbolAddress((void**)&xh, g_xh);
    cudaGetSymbolAddress((void**)&xl, g_xl);
    cudaGetSymbolAddress((void**)&wallh, g_wallh);
    cudaGetSymbolAddress((void**)&walll, g_walll);
    cudaGetSymbolAddress((void**)&woh, g_woh);
    cudaGetSymbolAddress((void**)&wol, g_wol);
    cudaGetSymbolAddress((void**)&qh, g_qh);
    cudaGetSymbolAddress((void**)&ql, g_ql);
    cudaGetSymbolAddress((void**)&kh, g_kh);
    cudaGetSymbolAddress((void**)&kl, g_kl);
    cudaGetSymbolAddress((void**)&vh, g_vh);
    cudaGetSymbolAddress((void**)&vl, g_vl);
    cudaGetSymbolAddress((void**)&ah, g_ah);
    cudaGetSymbolAddress((void**)&al, g_al);

    const int M = B_ * N_;   // 2048

    // Splits: x plain; Wq/Wk/Wv concatenated into [2048, 6144]; Wo plain
    {
        int t = B_ * N_ * D_ / 4;
        split4_kernel<<<(t + 255) / 256, 256>>>((const float4*)x, xh, xl, t);
        t = D_ * 4096 / 4;
        splitcat4_kernel<<<(t + 255) / 256, 256>>>(Wq, wallh, walll, 4096, QKV_W, 0, t);
        t = D_ * 1024 / 4;
        splitcat4_kernel<<<(t + 255) / 256, 256>>>(Wk, wallh, walll, 1024, QKV_W, 4096, t);
        splitcat4_kernel<<<(t + 255) / 256, 256>>>(Wv, wallh, walll, 1024, QKV_W, 5120, t);
        t = 4096 * D_ / 4;
        split4_kernel<<<(t + 255) / 256, 256>>>((const float4*)Wo, woh, wol, t);
    }

    cudaFuncSetAttribute(bgemm3_kernel,
                         cudaFuncAttributeMaxDynamicSharedMemorySize,
                         GEMM_SMEM_BYTES);

    // Fused QKV projection: [2048, 2048] x [2048, 6144]
    bgemm3_kernel<<<dim3(QKV_W / 128, M / 128), 256, GEMM_SMEM_BYTES>>>(
        xh, xl, wallh, walll, qkv, M, QKV_W, D_);

    // RoPE + convert; fold (1/sqrt(d))*log2(e) into q
    const float s2 = 0.08838834764831845f * 1.4426950408889634f;
    {
        int total_q = B_ * N_ * HI_ * 64;
        rope_split_kernel<<<(total_q + 255) / 256, 256>>>(
            qkv, qh, ql, HI_, total_q, s2, QKV_W, 0);
        int total_k = B_ * N_ * H_ * 64;
        rope_split_kernel<<<(total_k + 255) / 256, 256>>>(
            qkv, kh, kl, H_, total_k, 1.0f, QKV_W, 4096);
        int total_v4 = B_ * N_ * H_ * VD_ / 4;
        vsplit_kernel<<<(total_v4 + 255) / 256, 256>>>(qkv, vh, vl, total_v4);
    }

    cudaFuncSetAttribute(flash_mma_kernel,
                         cudaFuncAttributeMaxDynamicSharedMemorySize,
                         FLASH3_SMEM_BYTES);
    flash_mma_kernel<<<dim3(8, 64), 256, FLASH3_SMEM_BYTES>>>(
        qh, ql, kh, kl, vh, vl, ah, al);

    // Output projection: [2048, 4096] x [4096, 2048]
    bgemm3_kernel<<<dim3(2048 / 128, M / 128), 256, GEMM_SMEM_BYTES>>>(
        ah, al, woh, wol, out, M, 2048, 4096);
}